// round 13
// baseline (speedup 1.0000x reference)
#include <cuda_runtime.h>
#include <cuda_fp16.h>
#include <cstdint>

#define BB 2
#define SS 2048
#define DM 1024
#define NH 16
#define DK 64
#define NROWS (BB * SS)
#define OUT_ELEMS (NROWS * DM)
#define ATTN_ELEMS (2LL * 16 * 2048 * 2048)
#define INV_TEMP 0.35355339059327373f

typedef __half fp16;

// ------------------------- device scratch (no allocs) -----------------------
__device__ __align__(128) fp16  g_qn_hi[NROWS * DM];
__device__ __align__(128) fp16  g_ki_hi[NROWS * DM];
__device__ __align__(128) fp16  g_vi_hi[NROWS * DM];
__device__ __align__(128) fp16  g_wq_hi[DM * DM];
__device__ __align__(128) fp16  g_wk_hi[DM * DM];
__device__ __align__(128) fp16  g_wv_hi[DM * DM];
__device__ __align__(128) fp16  g_wf_hi[DM * DM];
__device__ __align__(128) fp16  g_qh_hi[NROWS * DM], g_qh_lo[NROWS * DM];
__device__ __align__(128) fp16  g_kh_hi[NROWS * DM], g_kh_lo[NROWS * DM];
__device__ __align__(128) fp16  g_vh_hi[NROWS * DM], g_vh_lo[NROWS * DM];
__device__ __align__(128) fp16  g_oh_hi[NROWS * DM];
__device__ __align__(128) float g_P[BB * NH * DK * DK];
__device__ int g_flag;

// ------------------------- helpers ------------------------------------------
__device__ __forceinline__ uint32_t smem_u32(const void* p) {
    uint32_t a;
    asm("{ .reg .u64 t; cvta.to.shared.u64 t, %1; cvt.u32.u64 %0, t; }"
        : "=r"(a) : "l"(p));
    return a;
}
__device__ __forceinline__ void cp16(uint32_t saddr, const void* g) {
    asm volatile("cp.async.cg.shared.global [%0], [%1], 16;"
                 :: "r"(saddr), "l"(g) : "memory");
}
__device__ __forceinline__ void cp_commit() {
    asm volatile("cp.async.commit_group;" ::: "memory");
}
__device__ __forceinline__ void cp_wait0() {
    asm volatile("cp.async.wait_group 0;" ::: "memory");
}
__device__ __forceinline__ void cp_wait1() {
    asm volatile("cp.async.wait_group 1;" ::: "memory");
}
__device__ __forceinline__ void ldsm4(uint32_t* r, uint32_t addr) {
    asm volatile("ldmatrix.sync.aligned.m8n8.x4.shared.b16 {%0,%1,%2,%3}, [%4];"
                 : "=r"(r[0]), "=r"(r[1]), "=r"(r[2]), "=r"(r[3]) : "r"(addr));
}
__device__ __forceinline__ void mma16816(float* d, const uint32_t* a,
                                         const uint32_t* b) {
    asm volatile(
        "mma.sync.aligned.m16n8k16.row.col.f32.f16.f16.f32 "
        "{%0,%1,%2,%3}, {%4,%5,%6,%7}, {%8,%9}, {%0,%1,%2,%3};"
        : "+f"(d[0]), "+f"(d[1]), "+f"(d[2]), "+f"(d[3])
        : "r"(a[0]), "r"(a[1]), "r"(a[2]), "r"(a[3]), "r"(b[0]), "r"(b[1]));
}
__device__ __forceinline__ void split_pair(float x, float y, __half2* hi,
                                           __half2* lo) {
    __half2 h = __floats2half2_rn(x, y);
    *hi = h;
    *lo = __floats2half2_rn(x - __half2float(__low2half(h)),
                            y - __half2float(__high2half(h)));
}

// ------------------------- small prep kernels --------------------------------
__global__ void initk() {
    int i = blockIdx.x * 256 + threadIdx.x;
    if (i < BB * NH * DK * DK) g_P[i] = 0.0f;
    if (i == 0) g_flag = 1;
}

// fallback full-mask check (only used when attn buffer absent)
__global__ void maskchk(const int* __restrict__ mask) {
    const int4* m4 = reinterpret_cast<const int4*>(mask);
    const size_t total = (size_t)BB * SS * SS / 4;
    size_t i = (size_t)blockIdx.x * 256 + threadIdx.x;
    size_t stride = (size_t)gridDim.x * 256;
    int bad = 0;
    for (size_t j = i; j < total; j += stride) {
        int4 m = __ldcs(&m4[j]);
        if (!(m.x && m.y && m.z && m.w)) bad = 1;
    }
    if (bad) g_flag = 0;
}

__global__ void ln_kernel(const float* __restrict__ q,
                          const float* __restrict__ gamma,
                          const float* __restrict__ beta,
                          fp16* __restrict__ out_hi) {
    __shared__ float red[16];
    const int row = blockIdx.x;
    const int tid = threadIdx.x;
    const float4 v = reinterpret_cast<const float4*>(q)[row * 256 + tid];
    float s  = v.x + v.y + v.z + v.w;
    float s2 = v.x * v.x + v.y * v.y + v.z * v.z + v.w * v.w;
    #pragma unroll
    for (int o = 16; o > 0; o >>= 1) {
        s  += __shfl_xor_sync(0xffffffffu, s,  o);
        s2 += __shfl_xor_sync(0xffffffffu, s2, o);
    }
    if ((tid & 31) == 0) { red[tid >> 5] = s; red[8 + (tid >> 5)] = s2; }
    __syncthreads();
    if (tid < 32) {
        s  = (tid < 8) ? red[tid]     : 0.0f;
        s2 = (tid < 8) ? red[8 + tid] : 0.0f;
        #pragma unroll
        for (int o = 4; o > 0; o >>= 1) {
            s  += __shfl_xor_sync(0xffffffffu, s,  o);
            s2 += __shfl_xor_sync(0xffffffffu, s2, o);
        }
        if (tid == 0) { red[0] = s; red[8] = s2; }
    }
    __syncthreads();
    const float mu   = red[0] * (1.0f / 1024.0f);
    const float var  = red[8] * (1.0f / 1024.0f) - mu * mu;
    const float rstd = rsqrtf(var + 1e-6f);
    const float4 g  = reinterpret_cast<const float4*>(gamma)[tid];
    const float4 bb = reinterpret_cast<const float4*>(beta)[tid];
    float y0 = ((v.x - mu) * rstd * g.x + bb.x) * INV_TEMP;
    float y1 = ((v.y - mu) * rstd * g.y + bb.y) * INV_TEMP;
    float y2 = ((v.z - mu) * rstd * g.z + bb.z) * INV_TEMP;
    float y3 = ((v.w - mu) * rstd * g.w + bb.w) * INV_TEMP;
    __half2* oh = reinterpret_cast<__half2*>(out_hi);
    const int b2 = (row * 256 + tid) * 2;
    oh[b2]     = __floats2half2_rn(y0, y1);
    oh[b2 + 1] = __floats2half2_rn(y2, y3);
}

// fp32 -> fp16 (hi only)
__global__ void cvtk(const float* __restrict__ x, fp16* __restrict__ hi, int n4) {
    int i = blockIdx.x * 256 + threadIdx.x;
    if (i >= n4) return;
    float4 v = reinterpret_cast<const float4*>(x)[i];
    reinterpret_cast<__half2*>(hi)[i * 2]     = __floats2half2_rn(v.x, v.y);
    reinterpret_cast<__half2*>(hi)[i * 2 + 1] = __floats2half2_rn(v.z, v.w);
}

// W[K][N] -> WT[n][k] hi fp16 (transpose)
__global__ void wprep(const float* __restrict__ W, fp16* __restrict__ Thi) {
    __shared__ float t[32][33];
    const int n0 = blockIdx.x * 32, k0 = blockIdx.y * 32;
    const int tx = threadIdx.x, ty = threadIdx.y;
    #pragma unroll
    for (int r = 0; r < 4; r++)
        t[ty + r * 8][tx] = W[(size_t)(k0 + ty + r * 8) * DM + n0 + tx];
    __syncthreads();
    #pragma unroll
    for (int r = 0; r < 4; r++) {
        const int nl = ty + r * 8;
        Thi[(size_t)(n0 + nl) * DM + k0 + tx] = __float2half_rn(t[tx][nl]);
    }
}

// ------------------------- mma.sync GEMM (fp16 1-term) -----------------------
// C[M,N] = A[M,K] @ B[N,K]^T. 128x128 CTA, BK=32, 2-stage, 2 CTAs/SM.
#define ROWB 80
#define BUFB (128 * ROWB)            // 10240
#define STAGEB (2 * BUFB)            // 20480
#define TG_SMEM (2 * STAGEB)         // 40960

__global__ __launch_bounds__(256, 2)
void tgemm(const fp16* __restrict__ A, const fp16* __restrict__ Bh,
           float* __restrict__ Cf, fp16* __restrict__ Chi, fp16* __restrict__ Clo,
           const float* __restrict__ resid, int N, int K)
{
    extern __shared__ __align__(128) char sb[];
    const uint32_t smb = smem_u32(sb);
    const int tid = threadIdx.x, lane = tid & 31, wid = tid >> 5;
    const int bm = blockIdx.y * 128, bn = blockIdx.x * 128;
    const int wm = (wid >> 2) * 64, wn = (wid & 3) * 32;

    uint32_t ldSm[4]; const fp16* ldG[4];
    #pragma unroll
    for (int i = 0; i < 4; i++) {
        const int buf = i >> 1;                       // 0=A, 1=B
        const int chunk = tid + (i & 1) * 256;        // 0..511
        const int r = chunk >> 2, j = chunk & 3;
        ldSm[i] = smb + buf * BUFB + r * ROWB + j * 16;
        const fp16* base = (buf == 0) ? A : Bh;
        const int rowg = (buf == 0) ? (bm + r) : (bn + r);
        ldG[i] = base + (size_t)rowg * K + j * 8;
    }

    const uint32_t aOff = (uint32_t)((wm + (lane & 15)) * ROWB + (((lane >> 4) << 3)) * 2);
    const uint32_t bOff = (uint32_t)(BUFB + (wn + ((lane >> 4) << 3) + (lane & 7)) * ROWB
                                     + ((((lane >> 3) & 1) << 3)) * 2);

    float acc[4][4][4] = {};
    const int NT = K / 32;

    #pragma unroll
    for (int i = 0; i < 4; i++) cp16(ldSm[i], ldG[i]);
    cp_commit();

    for (int t = 0; t < NT; t++) {
        if (t + 1 < NT) {
            const uint32_t so = ((t + 1) & 1) * STAGEB;
            const int kc = (t + 1) * 32;
            #pragma unroll
            for (int i = 0; i < 4; i++) cp16(ldSm[i] + so, ldG[i] + kc);
            cp_commit();
            cp_wait1();
        } else {
            cp_wait0();
        }
        __syncthreads();

        const uint32_t st = smb + (t & 1) * STAGEB;
        #pragma unroll
        for (int ks = 0; ks < 32; ks += 16) {
            uint32_t ah[4][4], bh2[2][4];
            #pragma unroll
            for (int mi = 0; mi < 4; mi++)
                ldsm4(ah[mi], st + aOff + mi * (16 * ROWB) + ks * 2);
            #pragma unroll
            for (int n2 = 0; n2 < 2; n2++)
                ldsm4(bh2[n2], st + bOff + n2 * (16 * ROWB) + ks * 2);
            #pragma unroll
            for (int mi = 0; mi < 4; mi++)
                #pragma unroll
                for (int ni = 0; ni < 4; ni++)
                    mma16816(acc[mi][ni], ah[mi], &bh2[ni >> 1][(ni & 1) * 2]);
        }
        __syncthreads();
    }

    #pragma unroll
    for (int mi = 0; mi < 4; mi++)
        #pragma unroll
        for (int ni = 0; ni < 4; ni++) {
            #pragma unroll
            for (int half = 0; half < 2; half++) {
                const int r = bm + wm + mi * 16 + (lane >> 2) + half * 8;
                const int c = bn + wn + ni * 8 + (lane & 3) * 2;
                const size_t idx = (size_t)r * N + c;
                float d0 = acc[mi][ni][half * 2 + 0];
                float d1 = acc[mi][ni][half * 2 + 1];
                if (resid) {
                    const float2 q2 = *reinterpret_cast<const float2*>(&resid[idx]);
                    d0 += q2.x; d1 += q2.y;
                }
                if (Cf) *reinterpret_cast<float2*>(&Cf[idx]) = make_float2(d0, d1);
                if (Chi) {
                    __half2 h, l;
                    split_pair(d0, d1, &h, &l);
                    *reinterpret_cast<__half2*>(&Chi[idx]) = h;
                    if (Clo) *reinterpret_cast<__half2*>(&Clo[idx]) = l;
                }
            }
        }
}

// ------------------------- S = Qhi Khi^T, 64(q) x 64(k) tile -----------------
// 35 KB smem -> ~4 CTAs/SM. Grid (h, ktile, b*32+qtile): mask tile L2-shared
// across the 16 heads. S-stage reuses the Q/K input region.
#define ROWS_S 144                      // 64 fp16 (128B) + 16B pad
#define KOFF2 (64 * ROWS_S)             // 9216
#define INEND (2 * 64 * ROWS_S)         // 18432
#define SROW2 68                        // S stage 64*68*4 = 17408 <= 18432
#define MOFF4 INEND                     // mask 16384
#define SA_SMEM (MOFF4 + 64 * 64 * 4)   // 34816

__global__ __launch_bounds__(256, 4)
void sgemm_attn(const fp16* __restrict__ Ahi, const fp16* __restrict__ Bh,
                const int* __restrict__ mask, float* __restrict__ attn)
{
    extern __shared__ __align__(128) char sb[];
    const uint32_t smb = smem_u32(sb);
    float* Ssm = reinterpret_cast<float*>(sb);
    const int tid = threadIdx.x, lane = tid & 31, wid = tid >> 5;
    const int h = blockIdx.x;
    const int k0t = blockIdx.y * 64;
    const int zz = blockIdx.z;
    const int b = zz >> 5;
    const int q0 = (zz & 31) * 64;
    const int bh = b * NH + h;
    const size_t hoff = (size_t)h * DK;
    const int wm = (wid >> 1) * 16, wn = (wid & 1) * 32;

    // group A: Q + K (512 chunks each, 2/thread each)
    #pragma unroll
    for (int i = 0; i < 2; i++) {
        const int chunk = tid + i * 256;
        const int r = chunk >> 3, j = chunk & 7;
        cp16(smb + r * ROWS_S + j * 16,
             Ahi + (size_t)(b * SS + q0 + r) * DM + hoff + j * 8);
        cp16(smb + KOFF2 + r * ROWS_S + j * 16,
             Bh + (size_t)(b * SS + k0t + r) * DM + hoff + j * 8);
    }
    cp_commit();

    // group B: mask tile 64x64 ints (1024 chunks, 4/thread)
    #pragma unroll
    for (int p = 0; p < 4; p++) {
        const int chunk = tid + p * 256;
        const int r = chunk >> 4, c4 = (chunk & 15) * 4;
        cp16(smb + MOFF4 + chunk * 16,
             &mask[((size_t)b * SS + q0 + r) * SS + k0t + c4]);
    }
    cp_commit();

    const uint32_t aOff = (uint32_t)((wm + (lane & 15)) * ROWS_S + (((lane >> 4) << 3)) * 2);
    const uint32_t bOff = (uint32_t)(KOFF2 + (wn + ((lane >> 4) << 3) + (lane & 7)) * ROWS_S
                                     + ((((lane >> 3) & 1) << 3)) * 2);

    cp_wait1();                      // inputs ready; mask still in flight
    __syncthreads();

    float acc[4][4] = {};
    #pragma unroll
    for (int ks = 0; ks < 64; ks += 16) {
        uint32_t ah[4], bh2[2][4];
        ldsm4(ah, smb + aOff + ks * 2);
        #pragma unroll
        for (int n2 = 0; n2 < 2; n2++)
            ldsm4(bh2[n2], smb + bOff + n2 * (16 * ROWS_S) + ks * 2);
        #pragma unroll
        for (int ni = 0; ni < 4; ni++)
            mma16816(acc[ni], ah, &bh2[ni >> 1][(ni & 1) * 2]);
    }

    // stage S tile into the (fully consumed) input region
    __syncthreads();
    #pragma unroll
    for (int ni = 0; ni < 4; ni++) {
        #pragma unroll
        for (int half = 0; half < 2; half++) {
            const int r = wm + (lane >> 2) + half * 8;
            const int c = wn + ni * 8 + (lane & 3) * 2;
            *reinterpret_cast<float2*>(&Ssm[r * SROW2 + c]) =
                make_float2(acc[ni][half * 2 + 0], acc[ni][half * 2 + 1]);
        }
    }
    cp_wait0();                      // mask tile resident
    __syncthreads();

    // coalesced streaming writes; mask read from smem only
    int bad = 0;
    #pragma unroll
    for (int p = 0; p < 4; p++) {
        const int chunk = tid + p * 256;
        const int r = chunk >> 4, c4 = (chunk & 15) * 4;
        float4 v = *reinterpret_cast<const float4*>(&Ssm[r * SROW2 + c4]);
        const int4 m = *reinterpret_cast<const int4*>(sb + MOFF4 + chunk * 16);
        if (m.x == 0) { v.x = -1e9f; bad = 1; }
        if (m.y == 0) { v.y = -1e9f; bad = 1; }
        if (m.z == 0) { v.z = -1e9f; bad = 1; }
        if (m.w == 0) { v.w = -1e9f; bad = 1; }
        __stcs(reinterpret_cast<float4*>(
                   &attn[((size_t)bh * SS + q0 + r) * SS + k0t + c4]), v);
    }
    if (__syncthreads_or(bad)) {
        if (tid == 0) atomicExch(&g_flag, 0);
    }
}

// ------------------------- P = K^T V (64x64 per bh), split-K -----------------
__global__ __launch_bounds__(256)
void pk_kernel()
{
    if (g_flag == 0) return;
    __shared__ float Ks[32][68];
    __shared__ float Vs[32][68];
    const int bh = blockIdx.x, split = blockIdx.y;
    const int b = bh >> 4, h = bh & 15;
    const size_t hoff = (size_t)h * DK;
    const int tid = threadIdx.x;
    const int tx = tid & 15, ty = tid >> 4;
    const __half2* khh = reinterpret_cast<const __half2*>(g_kh_hi);
    const __half2* khl = reinterpret_cast<const __half2*>(g_kh_lo);
    const __half2* vhh = reinterpret_cast<const __half2*>(g_vh_hi);
    const __half2* vhl = reinterpret_cast<const __half2*>(g_vh_lo);
    float acc[4][4] = {};
    for (int it = 0; it < 8; it++) {
        const int s0 = split * 256 + it * 32;
        __syncthreads();
        #pragma unroll
        for (int t = 0; t < 2; t++) {
            const int idx = tid + t * 256;
            const int rr = idx >> 4, c4 = idx & 15;
            const size_t g2 = ((size_t)(b * SS + s0 + rr) * DM + hoff) / 2 + c4 * 2;
            float2 kh0 = __half22float2(khh[g2]),     kl0 = __half22float2(khl[g2]);
            float2 kh1 = __half22float2(khh[g2 + 1]), kl1 = __half22float2(khl[g2 + 1]);
            Ks[rr][c4 * 4 + 0] = kh0.x + kl0.x; Ks[rr][c4 * 4 + 1] = kh0.y + kl0.y;
            Ks[rr][c4 * 4 + 2] = kh1.x + kl1.x; Ks[rr][c4 * 4 + 3] = kh1.y + kl1.y;
            float2 vh0 = __half22float2(vhh[g2]),     vl0 = __half22float2(vhl[g2]);
            float2 vh1 = __half22float2(vhh[g2 + 1]), vl1 = __half22float2(vhl[g2 + 1]);
            Vs[rr][c4 * 4 + 0] = vh0.x + vl0.x; Vs[rr][c4 * 4 + 1] = vh0.y + vl0.y;
            Vs[rr][c4 * 4 + 2] = vh1.x + vl1.x; Vs[rr][c4 * 4 + 3] = vh1.y + vl1.y;
        }
        __syncthreads();
        #pragma unroll 4
        for (int s = 0; s < 32; s++) {
            const float4 vv = *reinterpret_cast<const float4*>(&Vs[s][tx * 4]);
            #pragma unroll
            for (int i = 0; i < 4; i++) {
                const float kv = Ks[s][ty * 4 + i];
                acc[i][0] += kv * vv.x; acc[i][1] += kv * vv.y;
                acc[i][2] += kv * vv.z; acc[i][3] += kv * vv.w;
            }
        }
    }
    #pragma unroll
    for (int i = 0; i < 4; i++)
        #pragma unroll
        for (int j = 0; j < 4; j++)
            atomicAdd(&g_P[bh * (DK * DK) + (ty * 4 + i) * DK + tx * 4 + j], acc[i][j]);
}

// ------------------------- O = Qs @ P (fast path) ----------------------------
__global__ __launch_bounds__(256)
void ofast_kernel()
{
    if (g_flag == 0) return;
    __shared__ float Qs[64][68];
    __shared__ float Ps[64][64];
    const int q0 = blockIdx.x * 64;
    const int bh = blockIdx.y;
    const int b = bh >> 4, h = bh & 15;
    const size_t hoff = (size_t)h * DK;
    const int tid = threadIdx.x;
    const int tx = tid & 15, ty = tid >> 4;
    const __half2* qhh = reinterpret_cast<const __half2*>(g_qh_hi);
    const __half2* qhl = reinterpret_cast<const __half2*>(g_qh_lo);
    #pragma unroll
    for (int t = 0; t < 4; t++) {
        const int idx = tid + t * 256;
        const int rr = idx >> 4, c4 = idx & 15;
        const size_t g2 = ((size_t)(b * SS + q0 + rr) * DM + hoff) / 2 + c4 * 2;
        float2 h0 = __half22float2(qhh[g2]),     l0 = __half22float2(qhl[g2]);
        float2 h1 = __half22float2(qhh[g2 + 1]), l1 = __half22float2(qhl[g2 + 1]);
        Qs[rr][c4 * 4 + 0] = h0.x + l0.x; Qs[rr][c4 * 4 + 1] = h0.y + l0.y;
        Qs[rr][c4 * 4 + 2] = h1.x + l1.x; Qs[rr][c4 * 4 + 3] = h1.y + l1.y;
        *reinterpret_cast<float4*>(&Ps[rr][c4 * 4]) =
            reinterpret_cast<const float4*>(g_P)[(size_t)bh * (DK * DK) / 4 + rr * 16 + c4];
    }
    __syncthreads();
    float acc[4][4] = {};
    #pragma unroll 8
    for (int d = 0; d < 64; d++) {
        const float4 pv = *reinterpret_cast<const float4*>(&Ps[d][tx * 4]);
        #pragma unroll
        for (int i = 0; i < 4; i++) {
            const float qv = Qs[ty * 4 + i][d];
            acc[i][0] += qv * pv.x; acc[i][1] += qv * pv.y;
            acc[i][2] += qv * pv.z; acc[i][3] += qv * pv.w;
        }
    }
    #pragma unroll
    for (int i = 0; i < 4; i++) {
        const size_t base = (size_t)(b * SS + q0 + ty * 4 + i) * DM + hoff + tx * 4;
        __half2* ph = reinterpret_cast<__half2*>(&g_oh_hi[base]);
        ph[0] = __floats2half2_rn(acc[i][0], acc[i][1]);
        ph[1] = __floats2half2_rn(acc[i][2], acc[i][3]);
    }
}

// ------------------------- O = attn @ V (fallback) ---------------------------
__global__ __launch_bounds__(256)
void ofb_kernel(const float* __restrict__ attn)
{
    if (g_flag != 0) return;
    __shared__ float As[64][68];
    __shared__ float Vs[64][68];
    const int q0 = blockIdx.x * 64;
    const int bh = blockIdx.y;
    const int b = bh >> 4, h = bh & 15;
    const size_t hoff = (size_t)h * DK;
    const int tid = threadIdx.x;
    const int tx = tid & 15, ty = tid >> 4;
    const __half2* vhh = reinterpret_cast<const __half2*>(g_vh_hi);
    const __half2* vhl = reinterpret_cast<const __half2*>(g_vh_lo);
    float acc[4][4] = {};
    for (int k0 = 0; k0 < SS; k0 += 64) {
        __syncthreads();
        #pragma unroll
        for (int t = 0; t < 4; t++) {
            const int idx = tid + t * 256;
            const int rr = idx >> 4, c4 = idx & 15;
            *reinterpret_cast<float4*>(&As[rr][c4 * 4]) =
                reinterpret_cast<const float4*>(attn)[(((size_t)bh * SS + q0 + rr) * SS + k0) / 4 + c4];
            const size_t g2 = ((size_t)(b * SS + k0 + rr) * DM + hoff) / 2 + c4 * 2;
            float2 h0 = __half22float2(vhh[g2]),     l0 = __half22float2(vhl[g2]);
            float2 h1 = __half22float2(vhh[g2 + 1]), l1 = __half22float2(vhl[g2 + 1]);
            Vs[rr][c4 * 4 + 0] = h0.x + l0.x; Vs[rr][c4 * 4 + 1] = h0.y + l0.y;
            Vs[rr][c4 * 4 + 2] = h1.x + l1.x; Vs[rr][c4 * 4 + 3] = h1.y + l1.y;
        }
        __syncthreads();
        #pragma unroll 8
        for (int kk = 0; kk < 64; kk++) {
            const float4 vv = *reinterpret_cast<const float4*>(&Vs[kk][tx * 4]);
            #pragma unroll
            for (int i = 0; i < 4; i++) {
                const float sv = As[ty * 4 + i][kk];
                acc[i][0] += sv * vv.x; acc[i][1] += sv * vv.y;
                acc[i][2] += sv * vv.z; acc[i][3] += sv * vv.w;
            }
        }
    }
    #pragma unroll
    for (int i = 0; i < 4; i++) {
        const size_t base = (size_t)(b * SS + q0 + ty * 4 + i) * DM + hoff + tx * 4;
        __half2* ph = reinterpret_cast<__half2*>(&g_oh_hi[base]);
        ph[0] = __floats2half2_rn(acc[i][0], acc[i][1]);
        ph[1] = __floats2half2_rn(acc[i][2], acc[i][3]);
    }
}

// ---------------------------------------------------------------------------
extern "C" void kernel_launch(void* const* d_in, const int* in_sizes, int n_in,
                              void* d_out, int out_size)
{
    const float* q     = (const float*)d_in[0];
    const float* k     = (const float*)d_in[1];
    const float* v     = (const float*)d_in[2];
    const int*   mask  = (const int*)  d_in[3];
    const float* Wq    = (const float*)d_in[4];
    const float* Wk    = (const float*)d_in[5];
    const float* Wv    = (const float*)d_in[6];
    const float* Wfc   = (const float*)d_in[7];
    const float* gamma = (const float*)d_in[8];
    const float* beta  = (const float*)d_in[9];
    float* out = (float*)d_out;
    float* attn = ((long long)out_size >= (long long)OUT_ELEMS + ATTN_ELEMS)
                      ? out + OUT_ELEMS : nullptr;

    void* p;
    #define SYM(T, name, sym) cudaGetSymbolAddress(&p, sym); T* name = (T*)p
    SYM(fp16, qn_hi, g_qn_hi);
    SYM(fp16, ki_hi, g_ki_hi);
    SYM(fp16, vi_hi, g_vi_hi);
    SYM(fp16, wq_hi, g_wq_hi);
    SYM(fp16, wk_hi, g_wk_hi);
    SYM(fp16, wv_hi, g_wv_hi);
    SYM(fp16, wf_hi, g_wf_hi);
    SYM(fp16, qh_hi, g_qh_hi); SYM(fp16, qh_lo, g_qh_lo);
    SYM(fp16, kh_hi, g_kh_hi); SYM(fp16, kh_lo, g_kh_lo);
    SYM(fp16, vh_hi, g_vh_hi); SYM(fp16, vh_lo, g_vh_lo);
    SYM(fp16, oh_hi, g_oh_hi);
    #undef SYM

    cudaFuncSetAttribute(tgemm, cudaFuncAttributeMaxDynamicSharedMemorySize, TG_SMEM);
    cudaFuncSetAttribute(sgemm_attn, cudaFuncAttributeMaxDynamicSharedMemorySize, SA_SMEM);

    // prep
    initk<<<512, 256>>>();
    if (!attn) maskchk<<<2048, 256>>>(mask);
    ln_kernel<<<NROWS, 256>>>(q, gamma, beta, qn_hi);
    cvtk<<<NROWS * DM / 4 / 256, 256>>>(k, ki_hi, NROWS * DM / 4);
    cvtk<<<NROWS * DM / 4 / 256, 256>>>(v, vi_hi, NROWS * DM / 4);
    dim3 wg(32, 32), wb(32, 8);
    wprep<<<wg, wb>>>(Wq, wq_hi);
    wprep<<<wg, wb>>>(Wk, wk_hi);
    wprep<<<wg, wb>>>(Wv, wv_hi);
    wprep<<<wg, wb>>>(Wfc, wf_hi);

    // projections (fp16 1-term mma.sync, 2 CTAs/SM -> single wave)
    dim3 gg(DM / 128, NROWS / 128);
    tgemm<<<gg, 256, TG_SMEM>>>(qn_hi, wq_hi, nullptr, qh_hi, qh_lo, nullptr, DM, DM);
    tgemm<<<gg, 256, TG_SMEM>>>(ki_hi, wk_hi, nullptr, kh_hi, kh_lo, nullptr, DM, DM);
    tgemm<<<gg, 256, TG_SMEM>>>(vi_hi, wv_hi, nullptr, vh_hi, vh_lo, nullptr, DM, DM);

    // attn scores: 64x64 tiles, head-major grid for mask L2 reuse
    if (attn)
        sgemm_attn<<<dim3(NH, SS / 64, BB * (SS / 64)), 256, SA_SMEM>>>(
            qh_hi, kh_hi, mask, attn);

    // O: fast path (mask all-ones) or fallback
    pk_kernel<<<dim3(BB * NH, 8), 256>>>();
    ofast_kernel<<<dim3(SS / 64, BB * NH), 256>>>();
    if (attn)
        ofb_kernel<<<dim3(SS / 64, BB * NH), 256>>>(attn);

    // fc + residual (1-term)
    tgemm<<<gg, 256, TG_SMEM>>>(oh_hi, wf_hi, out, nullptr, nullptr, q, DM, DM);
}

// round 15
// speedup vs baseline: 1.5658x; 1.5658x over previous
#include <cuda_runtime.h>
#include <cuda_fp16.h>
#include <cstdint>

#define BB 2
#define SS 2048
#define DM 1024
#define NH 16
#define DK 64
#define NROWS (BB * SS)
#define OUT_ELEMS (NROWS * DM)
#define ATTN_ELEMS (2LL * 16 * 2048 * 2048)
#define INV_TEMP 0.35355339059327373f

typedef __half fp16;

// ------------------------- device scratch (no allocs) -----------------------
__device__ __align__(128) fp16  g_qn_hi[NROWS * DM];
__device__ __align__(128) fp16  g_ki_hi[NROWS * DM];
__device__ __align__(128) fp16  g_vi_hi[NROWS * DM];
__device__ __align__(128) fp16  g_wq_hi[DM * DM];
__device__ __align__(128) fp16  g_wk_hi[DM * DM];
__device__ __align__(128) fp16  g_wv_hi[DM * DM];
__device__ __align__(128) fp16  g_wf_hi[DM * DM];
__device__ __align__(128) fp16  g_qh_hi[NROWS * DM], g_qh_lo[NROWS * DM];
__device__ __align__(128) fp16  g_kh_hi[NROWS * DM], g_kh_lo[NROWS * DM];
__device__ __align__(128) fp16  g_vh_hi[NROWS * DM], g_vh_lo[NROWS * DM];
__device__ __align__(128) fp16  g_oh_hi[NROWS * DM];
__device__ __align__(128) float g_P[BB * NH * DK * DK];
__device__ int g_flag;

// ------------------------- helpers ------------------------------------------
__device__ __forceinline__ uint32_t smem_u32(const void* p) {
    uint32_t a;
    asm("{ .reg .u64 t; cvta.to.shared.u64 t, %1; cvt.u32.u64 %0, t; }"
        : "=r"(a) : "l"(p));
    return a;
}
__device__ __forceinline__ void cp16(uint32_t saddr, const void* g) {
    asm volatile("cp.async.cg.shared.global [%0], [%1], 16;"
                 :: "r"(saddr), "l"(g) : "memory");
}
__device__ __forceinline__ void cp_commit() {
    asm volatile("cp.async.commit_group;" ::: "memory");
}
__device__ __forceinline__ void cp_wait0() {
    asm volatile("cp.async.wait_group 0;" ::: "memory");
}
__device__ __forceinline__ void cp_wait1() {
    asm volatile("cp.async.wait_group 1;" ::: "memory");
}
__device__ __forceinline__ void cp_wait2() {
    asm volatile("cp.async.wait_group 2;" ::: "memory");
}
__device__ __forceinline__ void ldsm4(uint32_t* r, uint32_t addr) {
    asm volatile("ldmatrix.sync.aligned.m8n8.x4.shared.b16 {%0,%1,%2,%3}, [%4];"
                 : "=r"(r[0]), "=r"(r[1]), "=r"(r[2]), "=r"(r[3]) : "r"(addr));
}
__device__ __forceinline__ void mma16816(float* d, const uint32_t* a,
                                         const uint32_t* b) {
    asm volatile(
        "mma.sync.aligned.m16n8k16.row.col.f32.f16.f16.f32 "
        "{%0,%1,%2,%3}, {%4,%5,%6,%7}, {%8,%9}, {%0,%1,%2,%3};"
        : "+f"(d[0]), "+f"(d[1]), "+f"(d[2]), "+f"(d[3])
        : "r"(a[0]), "r"(a[1]), "r"(a[2]), "r"(a[3]), "r"(b[0]), "r"(b[1]));
}
__device__ __forceinline__ void split_pair(float x, float y, __half2* hi,
                                           __half2* lo) {
    __half2 h = __floats2half2_rn(x, y);
    *hi = h;
    *lo = __floats2half2_rn(x - __half2float(__low2half(h)),
                            y - __half2float(__high2half(h)));
}

// ------------------------- small prep kernels --------------------------------
__global__ void initk() {
    int i = blockIdx.x * 256 + threadIdx.x;
    if (i < BB * NH * DK * DK) g_P[i] = 0.0f;
    if (i == 0) g_flag = 1;
}

// fallback full-mask check (only used when attn buffer absent)
__global__ void maskchk(const int* __restrict__ mask) {
    const int4* m4 = reinterpret_cast<const int4*>(mask);
    const size_t total = (size_t)BB * SS * SS / 4;
    size_t i = (size_t)blockIdx.x * 256 + threadIdx.x;
    size_t stride = (size_t)gridDim.x * 256;
    int bad = 0;
    for (size_t j = i; j < total; j += stride) {
        int4 m = __ldcs(&m4[j]);
        if (!(m.x && m.y && m.z && m.w)) bad = 1;
    }
    if (bad) g_flag = 0;
}

__global__ void ln_kernel(const float* __restrict__ q,
                          const float* __restrict__ gamma,
                          const float* __restrict__ beta,
                          fp16* __restrict__ out_hi) {
    __shared__ float red[16];
    const int row = blockIdx.x;
    const int tid = threadIdx.x;
    const float4 v = reinterpret_cast<const float4*>(q)[row * 256 + tid];
    float s  = v.x + v.y + v.z + v.w;
    float s2 = v.x * v.x + v.y * v.y + v.z * v.z + v.w * v.w;
    #pragma unroll
    for (int o = 16; o > 0; o >>= 1) {
        s  += __shfl_xor_sync(0xffffffffu, s,  o);
        s2 += __shfl_xor_sync(0xffffffffu, s2, o);
    }
    if ((tid & 31) == 0) { red[tid >> 5] = s; red[8 + (tid >> 5)] = s2; }
    __syncthreads();
    if (tid < 32) {
        s  = (tid < 8) ? red[tid]     : 0.0f;
        s2 = (tid < 8) ? red[8 + tid] : 0.0f;
        #pragma unroll
        for (int o = 4; o > 0; o >>= 1) {
            s  += __shfl_xor_sync(0xffffffffu, s,  o);
            s2 += __shfl_xor_sync(0xffffffffu, s2, o);
        }
        if (tid == 0) { red[0] = s; red[8] = s2; }
    }
    __syncthreads();
    const float mu   = red[0] * (1.0f / 1024.0f);
    const float var  = red[8] * (1.0f / 1024.0f) - mu * mu;
    const float rstd = rsqrtf(var + 1e-6f);
    const float4 g  = reinterpret_cast<const float4*>(gamma)[tid];
    const float4 bb = reinterpret_cast<const float4*>(beta)[tid];
    float y0 = ((v.x - mu) * rstd * g.x + bb.x) * INV_TEMP;
    float y1 = ((v.y - mu) * rstd * g.y + bb.y) * INV_TEMP;
    float y2 = ((v.z - mu) * rstd * g.z + bb.z) * INV_TEMP;
    float y3 = ((v.w - mu) * rstd * g.w + bb.w) * INV_TEMP;
    __half2* oh = reinterpret_cast<__half2*>(out_hi);
    const int b2 = (row * 256 + tid) * 2;
    oh[b2]     = __floats2half2_rn(y0, y1);
    oh[b2 + 1] = __floats2half2_rn(y2, y3);
}

// fp32 -> fp16 (hi only)
__global__ void cvtk(const float* __restrict__ x, fp16* __restrict__ hi, int n4) {
    int i = blockIdx.x * 256 + threadIdx.x;
    if (i >= n4) return;
    float4 v = reinterpret_cast<const float4*>(x)[i];
    reinterpret_cast<__half2*>(hi)[i * 2]     = __floats2half2_rn(v.x, v.y);
    reinterpret_cast<__half2*>(hi)[i * 2 + 1] = __floats2half2_rn(v.z, v.w);
}

// W[K][N] -> WT[n][k] hi fp16 (transpose)
__global__ void wprep(const float* __restrict__ W, fp16* __restrict__ Thi) {
    __shared__ float t[32][33];
    const int n0 = blockIdx.x * 32, k0 = blockIdx.y * 32;
    const int tx = threadIdx.x, ty = threadIdx.y;
    #pragma unroll
    for (int r = 0; r < 4; r++)
        t[ty + r * 8][tx] = W[(size_t)(k0 + ty + r * 8) * DM + n0 + tx];
    __syncthreads();
    #pragma unroll
    for (int r = 0; r < 4; r++) {
        const int nl = ty + r * 8;
        Thi[(size_t)(n0 + nl) * DM + k0 + tx] = __float2half_rn(t[tx][nl]);
    }
}

// ------------------------- mma.sync GEMM (fp16 1-term, 3-stage) --------------
// C[M,N] = A[M,K] @ B[N,K]^T. 128x128 CTA, BK=32, 3-stage cp.async, occ 1.
#define ROWB 80
#define BUFB (128 * ROWB)            // 10240
#define STAGEB (2 * BUFB)            // 20480 (A + B)
#define TG_SMEM (3 * STAGEB)         // 61440

__global__ __launch_bounds__(256, 1)
void tgemm(const fp16* __restrict__ A, const fp16* __restrict__ Bh,
           float* __restrict__ Cf, fp16* __restrict__ Chi, fp16* __restrict__ Clo,
           const float* __restrict__ resid, int N, int K)
{
    extern __shared__ __align__(128) char sb[];
    const uint32_t smb = smem_u32(sb);
    const int tid = threadIdx.x, lane = tid & 31, wid = tid >> 5;
    const int bm = blockIdx.y * 128, bn = blockIdx.x * 128;
    const int wm = (wid >> 2) * 64, wn = (wid & 3) * 32;

    uint32_t ldSm[4]; const fp16* ldG[4];
    #pragma unroll
    for (int i = 0; i < 4; i++) {
        const int buf = i >> 1;                       // 0=A, 1=B
        const int chunk = tid + (i & 1) * 256;        // 0..511
        const int r = chunk >> 2, j = chunk & 3;
        ldSm[i] = smb + buf * BUFB + r * ROWB + j * 16;
        const fp16* base = (buf == 0) ? A : Bh;
        const int rowg = (buf == 0) ? (bm + r) : (bn + r);
        ldG[i] = base + (size_t)rowg * K + j * 8;
    }

    const uint32_t aOff = (uint32_t)((wm + (lane & 15)) * ROWB + (((lane >> 4) << 3)) * 2);
    const uint32_t bOff = (uint32_t)(BUFB + (wn + ((lane >> 4) << 3) + (lane & 7)) * ROWB
                                     + ((((lane >> 3) & 1) << 3)) * 2);

    float acc[4][4][4] = {};
    const int NT = K / 32;

    // preload stages 0,1
    #pragma unroll
    for (int s = 0; s < 2; s++) {
        #pragma unroll
        for (int i = 0; i < 4; i++) cp16(ldSm[i] + s * STAGEB, ldG[i] + s * 32);
        cp_commit();
    }

    int stage = 0;
    for (int t = 0; t < NT; t++) {
        if (t + 2 < NT) {
            const int ps = (stage + 2) % 3;
            const int kc = (t + 2) * 32;
            #pragma unroll
            for (int i = 0; i < 4; i++) cp16(ldSm[i] + ps * STAGEB, ldG[i] + kc);
            cp_commit();
            cp_wait2();
        } else if (t + 1 < NT) {
            cp_wait1();
        } else {
            cp_wait0();
        }
        __syncthreads();

        const uint32_t st = smb + stage * STAGEB;
        #pragma unroll
        for (int ks = 0; ks < 32; ks += 16) {
            uint32_t ah[4][4], bh2[2][4];
            #pragma unroll
            for (int mi = 0; mi < 4; mi++)
                ldsm4(ah[mi], st + aOff + mi * (16 * ROWB) + ks * 2);
            #pragma unroll
            for (int n2 = 0; n2 < 2; n2++)
                ldsm4(bh2[n2], st + bOff + n2 * (16 * ROWB) + ks * 2);
            #pragma unroll
            for (int mi = 0; mi < 4; mi++)
                #pragma unroll
                for (int ni = 0; ni < 4; ni++)
                    mma16816(acc[mi][ni], ah[mi], &bh2[ni >> 1][(ni & 1) * 2]);
        }
        __syncthreads();
        stage = (stage + 1) % 3;
    }

    #pragma unroll
    for (int mi = 0; mi < 4; mi++)
        #pragma unroll
        for (int ni = 0; ni < 4; ni++) {
            #pragma unroll
            for (int half = 0; half < 2; half++) {
                const int r = bm + wm + mi * 16 + (lane >> 2) + half * 8;
                const int c = bn + wn + ni * 8 + (lane & 3) * 2;
                const size_t idx = (size_t)r * N + c;
                float d0 = acc[mi][ni][half * 2 + 0];
                float d1 = acc[mi][ni][half * 2 + 1];
                if (resid) {
                    const float2 q2 = *reinterpret_cast<const float2*>(&resid[idx]);
                    d0 += q2.x; d1 += q2.y;
                }
                if (Cf) *reinterpret_cast<float2*>(&Cf[idx]) = make_float2(d0, d1);
                if (Chi) {
                    __half2 h, l;
                    split_pair(d0, d1, &h, &l);
                    *reinterpret_cast<__half2*>(&Chi[idx]) = h;
                    if (Clo) *reinterpret_cast<__half2*>(&Clo[idx]) = l;
                }
            }
        }
}

// ------------------------- S = Qhi Khi^T, 128(q) x 64(k) tile ----------------
// Round-12 config: single-term MMA, launch_bounds(256,2), head-major grid.
#define ROWS_S 144                      // 64 fp16 (128B) + 16B pad
#define BUFQ1 (128 * ROWS_S)            // 18432 (Qhi)
#define KOFF  BUFQ1                     // Khi at 18432 (9216 bytes)
#define SSTAGE (BUFQ1 + 64 * ROWS_S)    // 27648
#define SROW 68
#define MOFF3 (SSTAGE + 128 * SROW * 4) // 62464
#define SA_SMEM (MOFF3 + 128 * 64 * 4)  // 95232

__global__ __launch_bounds__(256, 2)
void sgemm_attn(const fp16* __restrict__ Ahi, const fp16* __restrict__ Bh,
                const int* __restrict__ mask, float* __restrict__ attn)
{
    extern __shared__ __align__(128) char sb[];
    const uint32_t smb = smem_u32(sb);
    float* Ssm = reinterpret_cast<float*>(sb + SSTAGE);
    const int tid = threadIdx.x, lane = tid & 31, wid = tid >> 5;
    const int h = blockIdx.x;
    const int k0t = blockIdx.y * 64;
    const int zz = blockIdx.z;
    const int b = zz >> 4;
    const int q0 = (zz & 15) * 128;
    const int bh = b * NH + h;
    const size_t hoff = (size_t)h * DK;
    const int wm = (wid >> 1) * 32, wn = (wid & 1) * 32;

    // group A: Qhi (1024 chunks, 4/thread) + Khi (512 chunks, 2/thread)
    #pragma unroll
    for (int i = 0; i < 4; i++) {
        const int chunk = tid + i * 256;
        const int r = chunk >> 3, j = chunk & 7;
        cp16(smb + r * ROWS_S + j * 16,
             Ahi + (size_t)(b * SS + q0 + r) * DM + hoff + j * 8);
    }
    #pragma unroll
    for (int i = 0; i < 2; i++) {
        const int chunk = tid + i * 256;
        const int r = chunk >> 3, j = chunk & 7;
        cp16(smb + KOFF + r * ROWS_S + j * 16,
             Bh + (size_t)(b * SS + k0t + r) * DM + hoff + j * 8);
    }
    cp_commit();

    // group B: mask tile 128x64 ints (2048 chunks, 8/thread)
    #pragma unroll
    for (int p = 0; p < 8; p++) {
        const int chunk = tid + p * 256;
        const int r = chunk >> 4, c4 = (chunk & 15) * 4;
        cp16(smb + MOFF3 + chunk * 16,
             &mask[((size_t)b * SS + q0 + r) * SS + k0t + c4]);
    }
    cp_commit();

    const uint32_t aOff = (uint32_t)((wm + (lane & 15)) * ROWS_S + (((lane >> 4) << 3)) * 2);
    const uint32_t bOff = (uint32_t)(KOFF + (wn + ((lane >> 4) << 3) + (lane & 7)) * ROWS_S
                                     + ((((lane >> 3) & 1) << 3)) * 2);

    cp_wait1();                      // inputs ready; mask still in flight
    __syncthreads();

    float acc[2][4][4] = {};
    #pragma unroll
    for (int ks = 0; ks < 64; ks += 16) {
        uint32_t ah[2][4], bh2[2][4];
        #pragma unroll
        for (int mi = 0; mi < 2; mi++)
            ldsm4(ah[mi], smb + aOff + mi * (16 * ROWS_S) + ks * 2);
        #pragma unroll
        for (int n2 = 0; n2 < 2; n2++)
            ldsm4(bh2[n2], smb + bOff + n2 * (16 * ROWS_S) + ks * 2);
        #pragma unroll
        for (int mi = 0; mi < 2; mi++)
            #pragma unroll
            for (int ni = 0; ni < 4; ni++)
                mma16816(acc[mi][ni], ah[mi], &bh2[ni >> 1][(ni & 1) * 2]);
    }

    // stage S tile to smem (separate region; no dependency on inputs)
    #pragma unroll
    for (int mi = 0; mi < 2; mi++)
        #pragma unroll
        for (int ni = 0; ni < 4; ni++) {
            #pragma unroll
            for (int half = 0; half < 2; half++) {
                const int r = wm + mi * 16 + (lane >> 2) + half * 8;
                const int c = wn + ni * 8 + (lane & 3) * 2;
                *reinterpret_cast<float2*>(&Ssm[r * SROW + c]) =
                    make_float2(acc[mi][ni][half * 2 + 0],
                                acc[mi][ni][half * 2 + 1]);
            }
        }
    cp_wait0();                      // mask tile resident
    __syncthreads();

    // coalesced streaming writes; mask read from smem only
    int bad = 0;
    #pragma unroll
    for (int p = 0; p < 8; p++) {
        const int chunk = tid + p * 256;
        const int r = chunk >> 4, c4 = (chunk & 15) * 4;
        float4 v = *reinterpret_cast<const float4*>(&Ssm[r * SROW + c4]);
        const int4 m = *reinterpret_cast<const int4*>(sb + MOFF3 + chunk * 16);
        if (m.x == 0) { v.x = -1e9f; bad = 1; }
        if (m.y == 0) { v.y = -1e9f; bad = 1; }
        if (m.z == 0) { v.z = -1e9f; bad = 1; }
        if (m.w == 0) { v.w = -1e9f; bad = 1; }
        __stcs(reinterpret_cast<float4*>(
                   &attn[((size_t)bh * SS + q0 + r) * SS + k0t + c4]), v);
    }
    if (__syncthreads_or(bad)) {
        if (tid == 0) atomicExch(&g_flag, 0);
    }
}

// ------------------------- P = K^T V (64x64 per bh), split-K -----------------
__global__ __launch_bounds__(256)
void pk_kernel()
{
    if (g_flag == 0) return;
    __shared__ float Ks[32][68];
    __shared__ float Vs[32][68];
    const int bh = blockIdx.x, split = blockIdx.y;
    const int b = bh >> 4, h = bh & 15;
    const size_t hoff = (size_t)h * DK;
    const int tid = threadIdx.x;
    const int tx = tid & 15, ty = tid >> 4;
    const __half2* khh = reinterpret_cast<const __half2*>(g_kh_hi);
    const __half2* khl = reinterpret_cast<const __half2*>(g_kh_lo);
    const __half2* vhh = reinterpret_cast<const __half2*>(g_vh_hi);
    const __half2* vhl = reinterpret_cast<const __half2*>(g_vh_lo);
    float acc[4][4] = {};
    for (int it = 0; it < 8; it++) {
        const int s0 = split * 256 + it * 32;
        __syncthreads();
        #pragma unroll
        for (int t = 0; t < 2; t++) {
            const int idx = tid + t * 256;
            const int rr = idx >> 4, c4 = idx & 15;
            const size_t g2 = ((size_t)(b * SS + s0 + rr) * DM + hoff) / 2 + c4 * 2;
            float2 kh0 = __half22float2(khh[g2]),     kl0 = __half22float2(khl[g2]);
            float2 kh1 = __half22float2(khh[g2 + 1]), kl1 = __half22float2(khl[g2 + 1]);
            Ks[rr][c4 * 4 + 0] = kh0.x + kl0.x; Ks[rr][c4 * 4 + 1] = kh0.y + kl0.y;
            Ks[rr][c4 * 4 + 2] = kh1.x + kl1.x; Ks[rr][c4 * 4 + 3] = kh1.y + kl1.y;
            float2 vh0 = __half22float2(vhh[g2]),     vl0 = __half22float2(vhl[g2]);
            float2 vh1 = __half22float2(vhh[g2 + 1]), vl1 = __half22float2(vhl[g2 + 1]);
            Vs[rr][c4 * 4 + 0] = vh0.x + vl0.x; Vs[rr][c4 * 4 + 1] = vh0.y + vl0.y;
            Vs[rr][c4 * 4 + 2] = vh1.x + vl1.x; Vs[rr][c4 * 4 + 3] = vh1.y + vl1.y;
        }
        __syncthreads();
        #pragma unroll 4
        for (int s = 0; s < 32; s++) {
            const float4 vv = *reinterpret_cast<const float4*>(&Vs[s][tx * 4]);
            #pragma unroll
            for (int i = 0; i < 4; i++) {
                const float kv = Ks[s][ty * 4 + i];
                acc[i][0] += kv * vv.x; acc[i][1] += kv * vv.y;
                acc[i][2] += kv * vv.z; acc[i][3] += kv * vv.w;
            }
        }
    }
    #pragma unroll
    for (int i = 0; i < 4; i++)
        #pragma unroll
        for (int j = 0; j < 4; j++)
            atomicAdd(&g_P[bh * (DK * DK) + (ty * 4 + i) * DK + tx * 4 + j], acc[i][j]);
}

// ------------------------- O = Qs @ P (fast path) ----------------------------
__global__ __launch_bounds__(256)
void ofast_kernel()
{
    if (g_flag == 0) return;
    __shared__ float Qs[64][68];
    __shared__ float Ps[64][64];
    const int q0 = blockIdx.x * 64;
    const int bh = blockIdx.y;
    const int b = bh >> 4, h = bh & 15;
    const size_t hoff = (size_t)h * DK;
    const int tid = threadIdx.x;
    const int tx = tid & 15, ty = tid >> 4;
    const __half2* qhh = reinterpret_cast<const __half2*>(g_qh_hi);
    const __half2* qhl = reinterpret_cast<const __half2*>(g_qh_lo);
    #pragma unroll
    for (int t = 0; t < 4; t++) {
        const int idx = tid + t * 256;
        const int rr = idx >> 4, c4 = idx & 15;
        const size_t g2 = ((size_t)(b * SS + q0 + rr) * DM + hoff) / 2 + c4 * 2;
        float2 h0 = __half22float2(qhh[g2]),     l0 = __half22float2(qhl[g2]);
        float2 h1 = __half22float2(qhh[g2 + 1]), l1 = __half22float2(qhl[g2 + 1]);
        Qs[rr][c4 * 4 + 0] = h0.x + l0.x; Qs[rr][c4 * 4 + 1] = h0.y + l0.y;
        Qs[rr][c4 * 4 + 2] = h1.x + l1.x; Qs[rr][c4 * 4 + 3] = h1.y + l1.y;
        *reinterpret_cast<float4*>(&Ps[rr][c4 * 4]) =
            reinterpret_cast<const float4*>(g_P)[(size_t)bh * (DK * DK) / 4 + rr * 16 + c4];
    }
    __syncthreads();
    float acc[4][4] = {};
    #pragma unroll 8
    for (int d = 0; d < 64; d++) {
        const float4 pv = *reinterpret_cast<const float4*>(&Ps[d][tx * 4]);
        #pragma unroll
        for (int i = 0; i < 4; i++) {
            const float qv = Qs[ty * 4 + i][d];
            acc[i][0] += qv * pv.x; acc[i][1] += qv * pv.y;
            acc[i][2] += qv * pv.z; acc[i][3] += qv * pv.w;
        }
    }
    #pragma unroll
    for (int i = 0; i < 4; i++) {
        const size_t base = (size_t)(b * SS + q0 + ty * 4 + i) * DM + hoff + tx * 4;
        __half2* ph = reinterpret_cast<__half2*>(&g_oh_hi[base]);
        ph[0] = __floats2half2_rn(acc[i][0], acc[i][1]);
        ph[1] = __floats2half2_rn(acc[i][2], acc[i][3]);
    }
}

// ------------------------- O = attn @ V (fallback) ---------------------------
__global__ __launch_bounds__(256)
void ofb_kernel(const float* __restrict__ attn)
{
    if (g_flag != 0) return;
    __shared__ float As[64][68];
    __shared__ float Vs[64][68];
    const int q0 = blockIdx.x * 64;
    const int bh = blockIdx.y;
    const int b = bh >> 4, h = bh & 15;
    const size_t hoff = (size_t)h * DK;
    const int tid = threadIdx.x;
    const int tx = tid & 15, ty = tid >> 4;
    const __half2* vhh = reinterpret_cast<const __half2*>(g_vh_hi);
    const __half2* vhl = reinterpret_cast<const __half2*>(g_vh_lo);
    float acc[4][4] = {};
    for (int k0 = 0; k0 < SS; k0 += 64) {
        __syncthreads();
        #pragma unroll
        for (int t = 0; t < 4; t++) {
            const int idx = tid + t * 256;
            const int rr = idx >> 4, c4 = idx & 15;
            *reinterpret_cast<float4*>(&As[rr][c4 * 4]) =
                reinterpret_cast<const float4*>(attn)[(((size_t)bh * SS + q0 + rr) * SS + k0) / 4 + c4];
            const size_t g2 = ((size_t)(b * SS + k0 + rr) * DM + hoff) / 2 + c4 * 2;
            float2 h0 = __half22float2(vhh[g2]),     l0 = __half22float2(vhl[g2]);
            float2 h1 = __half22float2(vhh[g2 + 1]), l1 = __half22float2(vhl[g2 + 1]);
            Vs[rr][c4 * 4 + 0] = h0.x + l0.x; Vs[rr][c4 * 4 + 1] = h0.y + l0.y;
            Vs[rr][c4 * 4 + 2] = h1.x + l1.x; Vs[rr][c4 * 4 + 3] = h1.y + l1.y;
        }
        __syncthreads();
        #pragma unroll 8
        for (int kk = 0; kk < 64; kk++) {
            const float4 vv = *reinterpret_cast<const float4*>(&Vs[kk][tx * 4]);
            #pragma unroll
            for (int i = 0; i < 4; i++) {
                const float sv = As[ty * 4 + i][kk];
                acc[i][0] += sv * vv.x; acc[i][1] += sv * vv.y;
                acc[i][2] += sv * vv.z; acc[i][3] += sv * vv.w;
            }
        }
    }
    #pragma unroll
    for (int i = 0; i < 4; i++) {
        const size_t base = (size_t)(b * SS + q0 + ty * 4 + i) * DM + hoff + tx * 4;
        __half2* ph = reinterpret_cast<__half2*>(&g_oh_hi[base]);
        ph[0] = __floats2half2_rn(acc[i][0], acc[i][1]);
        ph[1] = __floats2half2_rn(acc[i][2], acc[i][3]);
    }
}

// ---------------------------------------------------------------------------
extern "C" void kernel_launch(void* const* d_in, const int* in_sizes, int n_in,
                              void* d_out, int out_size)
{
    const float* q     = (const float*)d_in[0];
    const float* k     = (const float*)d_in[1];
    const float* v     = (const float*)d_in[2];
    const int*   mask  = (const int*)  d_in[3];
    const float* Wq    = (const float*)d_in[4];
    const float* Wk    = (const float*)d_in[5];
    const float* Wv    = (const float*)d_in[6];
    const float* Wfc   = (const float*)d_in[7];
    const float* gamma = (const float*)d_in[8];
    const float* beta  = (const float*)d_in[9];
    float* out = (float*)d_out;
    float* attn = ((long long)out_size >= (long long)OUT_ELEMS + ATTN_ELEMS)
                      ? out + OUT_ELEMS : nullptr;

    void* p;
    #define SYM(T, name, sym) cudaGetSymbolAddress(&p, sym); T* name = (T*)p
    SYM(fp16, qn_hi, g_qn_hi);
    SYM(fp16, ki_hi, g_ki_hi);
    SYM(fp16, vi_hi, g_vi_hi);
    SYM(fp16, wq_hi, g_wq_hi);
    SYM(fp16, wk_hi, g_wk_hi);
    SYM(fp16, wv_hi, g_wv_hi);
    SYM(fp16, wf_hi, g_wf_hi);
    SYM(fp16, qh_hi, g_qh_hi); SYM(fp16, qh_lo, g_qh_lo);
    SYM(fp16, kh_hi, g_kh_hi); SYM(fp16, kh_lo, g_kh_lo);
    SYM(fp16, vh_hi, g_vh_hi); SYM(fp16, vh_lo, g_vh_lo);
    SYM(fp16, oh_hi, g_oh_hi);
    #undef SYM

    cudaFuncSetAttribute(tgemm, cudaFuncAttributeMaxDynamicSharedMemorySize, TG_SMEM);
    cudaFuncSetAttribute(sgemm_attn, cudaFuncAttributeMaxDynamicSharedMemorySize, SA_SMEM);

    // prep
    initk<<<512, 256>>>();
    if (!attn) maskchk<<<2048, 256>>>(mask);
    ln_kernel<<<NROWS, 256>>>(q, gamma, beta, qn_hi);
    cvtk<<<NROWS * DM / 4 / 256, 256>>>(k, ki_hi, NROWS * DM / 4);
    cvtk<<<NROWS * DM / 4 / 256, 256>>>(v, vi_hi, NROWS * DM / 4);
    dim3 wg(32, 32), wb(32, 8);
    wprep<<<wg, wb>>>(Wq, wq_hi);
    wprep<<<wg, wb>>>(Wk, wk_hi);
    wprep<<<wg, wb>>>(Wv, wv_hi);
    wprep<<<wg, wb>>>(Wfc, wf_hi);

    // projections (fp16 1-term mma.sync, 3-stage pipeline, occ 1)
    dim3 gg(DM / 128, NROWS / 128);
    tgemm<<<gg, 256, TG_SMEM>>>(qn_hi, wq_hi, nullptr, qh_hi, qh_lo, nullptr, DM, DM);
    tgemm<<<gg, 256, TG_SMEM>>>(ki_hi, wk_hi, nullptr, kh_hi, kh_lo, nullptr, DM, DM);
    tgemm<<<gg, 256, TG_SMEM>>>(vi_hi, wv_hi, nullptr, vh_hi, vh_lo, nullptr, DM, DM);

    // attn scores: round-12 config (128x64, occ 2, head-major grid)
    if (attn)
        sgemm_attn<<<dim3(NH, SS / 64, BB * (SS / 128)), 256, SA_SMEM>>>(
            qh_hi, kh_hi, mask, attn);

    // O: fast path (mask all-ones) or fallback
    pk_kernel<<<dim3(BB * NH, 8), 256>>>();
    ofast_kernel<<<dim3(SS / 64, BB * NH), 256>>>();
    if (attn)
        ofb_kernel<<<dim3(SS / 64, BB * NH), 256>>>(attn);

    // fc + residual (1-term)
    tgemm<<<gg, 256, TG_SMEM>>>(oh_hi, wf_hi, out, nullptr, nullptr, q, DM, DM);
}

// round 16
// speedup vs baseline: 1.7036x; 1.0880x over previous
#include <cuda_runtime.h>
#include <cuda_fp16.h>
#include <cstdint>

#define BB 2
#define SS 2048
#define DM 1024
#define NH 16
#define DK 64
#define NROWS (BB * SS)
#define OUT_ELEMS (NROWS * DM)
#define ATTN_ELEMS (2LL * 16 * 2048 * 2048)
#define INV_TEMP 0.35355339059327373f

typedef __half fp16;

// ------------------------- device scratch (no allocs) -----------------------
__device__ __align__(128) fp16  g_qn_hi[NROWS * DM];
__device__ __align__(128) fp16  g_ki_hi[NROWS * DM];
__device__ __align__(128) fp16  g_vi_hi[NROWS * DM];
__device__ __align__(128) fp16  g_wq_hi[DM * DM];
__device__ __align__(128) fp16  g_wk_hi[DM * DM];
__device__ __align__(128) fp16  g_wv_hi[DM * DM];
__device__ __align__(128) fp16  g_wf_hi[DM * DM];
__device__ __align__(128) fp16  g_qh_hi[NROWS * DM], g_qh_lo[NROWS * DM];
__device__ __align__(128) fp16  g_kh_hi[NROWS * DM], g_kh_lo[NROWS * DM];
__device__ __align__(128) fp16  g_vh_hi[NROWS * DM], g_vh_lo[NROWS * DM];
__device__ __align__(128) fp16  g_oh_hi[NROWS * DM];
__device__ __align__(128) float g_P[BB * NH * DK * DK];
__device__ int g_flag;

// ------------------------- helpers ------------------------------------------
__device__ __forceinline__ uint32_t smem_u32(const void* p) {
    uint32_t a;
    asm("{ .reg .u64 t; cvta.to.shared.u64 t, %1; cvt.u32.u64 %0, t; }"
        : "=r"(a) : "l"(p));
    return a;
}
__device__ __forceinline__ void cp16(uint32_t saddr, const void* g) {
    asm volatile("cp.async.cg.shared.global [%0], [%1], 16;"
                 :: "r"(saddr), "l"(g) : "memory");
}
__device__ __forceinline__ void cp_commit() {
    asm volatile("cp.async.commit_group;" ::: "memory");
}
__device__ __forceinline__ void cp_wait0() {
    asm volatile("cp.async.wait_group 0;" ::: "memory");
}
__device__ __forceinline__ void cp_wait1() {
    asm volatile("cp.async.wait_group 1;" ::: "memory");
}
__device__ __forceinline__ void cp_wait2() {
    asm volatile("cp.async.wait_group 2;" ::: "memory");
}
__device__ __forceinline__ void ldsm4(uint32_t* r, uint32_t addr) {
    asm volatile("ldmatrix.sync.aligned.m8n8.x4.shared.b16 {%0,%1,%2,%3}, [%4];"
                 : "=r"(r[0]), "=r"(r[1]), "=r"(r[2]), "=r"(r[3]) : "r"(addr));
}
__device__ __forceinline__ void mma16816(float* d, const uint32_t* a,
                                         const uint32_t* b) {
    asm volatile(
        "mma.sync.aligned.m16n8k16.row.col.f32.f16.f16.f32 "
        "{%0,%1,%2,%3}, {%4,%5,%6,%7}, {%8,%9}, {%0,%1,%2,%3};"
        : "+f"(d[0]), "+f"(d[1]), "+f"(d[2]), "+f"(d[3])
        : "r"(a[0]), "r"(a[1]), "r"(a[2]), "r"(a[3]), "r"(b[0]), "r"(b[1]));
}
__device__ __forceinline__ void split_pair(float x, float y, __half2* hi,
                                           __half2* lo) {
    __half2 h = __floats2half2_rn(x, y);
    *hi = h;
    *lo = __floats2half2_rn(x - __half2float(__low2half(h)),
                            y - __half2float(__high2half(h)));
}

// ------------------------- small prep kernels --------------------------------
__global__ void initk() {
    int i = blockIdx.x * 256 + threadIdx.x;
    if (i < BB * NH * DK * DK) g_P[i] = 0.0f;
    if (i == 0) g_flag = 1;
}

// fallback full-mask check (only used when attn buffer absent)
__global__ void maskchk(const int* __restrict__ mask) {
    const int4* m4 = reinterpret_cast<const int4*>(mask);
    const size_t total = (size_t)BB * SS * SS / 4;
    size_t i = (size_t)blockIdx.x * 256 + threadIdx.x;
    size_t stride = (size_t)gridDim.x * 256;
    int bad = 0;
    for (size_t j = i; j < total; j += stride) {
        int4 m = __ldcs(&m4[j]);
        if (!(m.x && m.y && m.z && m.w)) bad = 1;
    }
    if (bad) g_flag = 0;
}

__global__ void ln_kernel(const float* __restrict__ q,
                          const float* __restrict__ gamma,
                          const float* __restrict__ beta,
                          fp16* __restrict__ out_hi) {
    __shared__ float red[16];
    const int row = blockIdx.x;
    const int tid = threadIdx.x;
    const float4 v = reinterpret_cast<const float4*>(q)[row * 256 + tid];
    float s  = v.x + v.y + v.z + v.w;
    float s2 = v.x * v.x + v.y * v.y + v.z * v.z + v.w * v.w;
    #pragma unroll
    for (int o = 16; o > 0; o >>= 1) {
        s  += __shfl_xor_sync(0xffffffffu, s,  o);
        s2 += __shfl_xor_sync(0xffffffffu, s2, o);
    }
    if ((tid & 31) == 0) { red[tid >> 5] = s; red[8 + (tid >> 5)] = s2; }
    __syncthreads();
    if (tid < 32) {
        s  = (tid < 8) ? red[tid]     : 0.0f;
        s2 = (tid < 8) ? red[8 + tid] : 0.0f;
        #pragma unroll
        for (int o = 4; o > 0; o >>= 1) {
            s  += __shfl_xor_sync(0xffffffffu, s,  o);
            s2 += __shfl_xor_sync(0xffffffffu, s2, o);
        }
        if (tid == 0) { red[0] = s; red[8] = s2; }
    }
    __syncthreads();
    const float mu   = red[0] * (1.0f / 1024.0f);
    const float var  = red[8] * (1.0f / 1024.0f) - mu * mu;
    const float rstd = rsqrtf(var + 1e-6f);
    const float4 g  = reinterpret_cast<const float4*>(gamma)[tid];
    const float4 bb = reinterpret_cast<const float4*>(beta)[tid];
    float y0 = ((v.x - mu) * rstd * g.x + bb.x) * INV_TEMP;
    float y1 = ((v.y - mu) * rstd * g.y + bb.y) * INV_TEMP;
    float y2 = ((v.z - mu) * rstd * g.z + bb.z) * INV_TEMP;
    float y3 = ((v.w - mu) * rstd * g.w + bb.w) * INV_TEMP;
    __half2* oh = reinterpret_cast<__half2*>(out_hi);
    const int b2 = (row * 256 + tid) * 2;
    oh[b2]     = __floats2half2_rn(y0, y1);
    oh[b2 + 1] = __floats2half2_rn(y2, y3);
}

// fp32 -> fp16 for k and v in one launch (blockIdx.y selects)
__global__ void cvt2k(const float* __restrict__ k, const float* __restrict__ v,
                      fp16* __restrict__ khi, fp16* __restrict__ vhi, int n4) {
    int i = blockIdx.x * 256 + threadIdx.x;
    if (i >= n4) return;
    const float* x = blockIdx.y ? v : k;
    fp16* hi = blockIdx.y ? vhi : khi;
    float4 t = reinterpret_cast<const float4*>(x)[i];
    reinterpret_cast<__half2*>(hi)[i * 2]     = __floats2half2_rn(t.x, t.y);
    reinterpret_cast<__half2*>(hi)[i * 2 + 1] = __floats2half2_rn(t.z, t.w);
}

// W[K][N] -> WT[n][k] fp16 for 4 weight matrices (blockIdx.z selects)
__global__ void wprep4(const float* __restrict__ W0, const float* __restrict__ W1,
                       const float* __restrict__ W2, const float* __restrict__ W3,
                       fp16* __restrict__ T0, fp16* __restrict__ T1,
                       fp16* __restrict__ T2, fp16* __restrict__ T3) {
    __shared__ float t[32][33];
    const float* W = (blockIdx.z == 0) ? W0 : (blockIdx.z == 1) ? W1
                   : (blockIdx.z == 2) ? W2 : W3;
    fp16* T = (blockIdx.z == 0) ? T0 : (blockIdx.z == 1) ? T1
            : (blockIdx.z == 2) ? T2 : T3;
    const int n0 = blockIdx.x * 32, k0 = blockIdx.y * 32;
    const int tx = threadIdx.x, ty = threadIdx.y;
    #pragma unroll
    for (int r = 0; r < 4; r++)
        t[ty + r * 8][tx] = W[(size_t)(k0 + ty + r * 8) * DM + n0 + tx];
    __syncthreads();
    #pragma unroll
    for (int r = 0; r < 4; r++) {
        const int nl = ty + r * 8;
        T[(size_t)(n0 + nl) * DM + k0 + tx] = __float2half_rn(t[tx][nl]);
    }
}

// ------------------------- mma.sync GEMM (fp16 1-term, 3-stage) --------------
// C[M,N] = A[M,K] @ B[N,K]^T. 128(M)x256(N) CTA, BK=32, 3-stage, 128 blocks
// per GEMM = single wave. Warp tile 64x64.
#define ROWB 80
#define ABUF (128 * ROWB)            // 10240
#define BBUF (256 * ROWB)            // 20480
#define STAGEB (ABUF + BBUF)         // 30720
#define TG_SMEM (3 * STAGEB)         // 92160

__global__ __launch_bounds__(256, 1)
void tgemm(const fp16* __restrict__ A, const fp16* __restrict__ Bh,
           float* __restrict__ Cf, fp16* __restrict__ Chi, fp16* __restrict__ Clo,
           const float* __restrict__ resid, int N, int K)
{
    extern __shared__ __align__(128) char sb[];
    const uint32_t smb = smem_u32(sb);
    const int tid = threadIdx.x, lane = tid & 31, wid = tid >> 5;
    const int bm = blockIdx.y * 128, bn = blockIdx.x * 256;
    const int wm = (wid >> 2) * 64, wn = (wid & 3) * 64;

    // per-stage loads: A 512 chunks (2/thread), B 1024 chunks (4/thread)
    uint32_t ldSm[6]; const fp16* ldG[6];
    #pragma unroll
    for (int i = 0; i < 6; i++) {
        const int isB = (i >= 2);
        const int chunk = tid + (isB ? (i - 2) : i) * 256;
        const int r = chunk >> 2, j = chunk & 3;
        ldSm[i] = smb + (isB ? ABUF : 0) + r * ROWB + j * 16;
        ldG[i] = (isB ? Bh + (size_t)(bn + r) * K : A + (size_t)(bm + r) * K) + j * 8;
    }

    const uint32_t aOff = (uint32_t)((wm + (lane & 15)) * ROWB + (((lane >> 4) << 3)) * 2);
    const uint32_t bOff = (uint32_t)(ABUF + (wn + ((lane >> 4) << 3) + (lane & 7)) * ROWB
                                     + ((((lane >> 3) & 1) << 3)) * 2);

    float acc[4][8][4] = {};
    const int NT = K / 32;

    // preload stages 0,1
    #pragma unroll
    for (int s = 0; s < 2; s++) {
        #pragma unroll
        for (int i = 0; i < 6; i++) cp16(ldSm[i] + s * STAGEB, ldG[i] + s * 32);
        cp_commit();
    }

    int stage = 0;
    for (int t = 0; t < NT; t++) {
        if (t + 2 < NT) {
            const int ps = (stage + 2) % 3;
            const int kc = (t + 2) * 32;
            #pragma unroll
            for (int i = 0; i < 6; i++) cp16(ldSm[i] + ps * STAGEB, ldG[i] + kc);
            cp_commit();
            cp_wait2();
        } else if (t + 1 < NT) {
            cp_wait1();
        } else {
            cp_wait0();
        }
        __syncthreads();

        const uint32_t st = smb + stage * STAGEB;
        #pragma unroll
        for (int ks = 0; ks < 32; ks += 16) {
            uint32_t ah[4][4], bh2[4][4];
            #pragma unroll
            for (int mi = 0; mi < 4; mi++)
                ldsm4(ah[mi], st + aOff + mi * (16 * ROWB) + ks * 2);
            #pragma unroll
            for (int n2 = 0; n2 < 4; n2++)
                ldsm4(bh2[n2], st + bOff + n2 * (16 * ROWB) + ks * 2);
            #pragma unroll
            for (int mi = 0; mi < 4; mi++)
                #pragma unroll
                for (int ni = 0; ni < 8; ni++)
                    mma16816(acc[mi][ni], ah[mi], &bh2[ni >> 1][(ni & 1) * 2]);
        }
        __syncthreads();
        stage = (stage + 1) % 3;
    }

    #pragma unroll
    for (int mi = 0; mi < 4; mi++)
        #pragma unroll
        for (int ni = 0; ni < 8; ni++) {
            #pragma unroll
            for (int half = 0; half < 2; half++) {
                const int r = bm + wm + mi * 16 + (lane >> 2) + half * 8;
                const int c = bn + wn + ni * 8 + (lane & 3) * 2;
                const size_t idx = (size_t)r * N + c;
                float d0 = acc[mi][ni][half * 2 + 0];
                float d1 = acc[mi][ni][half * 2 + 1];
                if (resid) {
                    const float2 q2 = *reinterpret_cast<const float2*>(&resid[idx]);
                    d0 += q2.x; d1 += q2.y;
                }
                if (Cf) *reinterpret_cast<float2*>(&Cf[idx]) = make_float2(d0, d1);
                if (Chi) {
                    __half2 h, l;
                    split_pair(d0, d1, &h, &l);
                    *reinterpret_cast<__half2*>(&Chi[idx]) = h;
                    if (Clo) *reinterpret_cast<__half2*>(&Clo[idx]) = l;
                }
            }
        }
}

// ------------------------- S = Qhi Khi^T, 128(q) x 64(k) tile ----------------
// Single-term MMA, launch_bounds(256,2), head-major grid (mask L2 reuse).
#define ROWS_S 144                      // 64 fp16 (128B) + 16B pad
#define BUFQ1 (128 * ROWS_S)            // 18432 (Qhi)
#define KOFF  BUFQ1                     // Khi at 18432 (9216 bytes)
#define SSTAGE (BUFQ1 + 64 * ROWS_S)    // 27648
#define SROW 68
#define MOFF3 (SSTAGE + 128 * SROW * 4) // 62464
#define SA_SMEM (MOFF3 + 128 * 64 * 4)  // 95232

__global__ __launch_bounds__(256, 2)
void sgemm_attn(const fp16* __restrict__ Ahi, const fp16* __restrict__ Bh,
                const int* __restrict__ mask, float* __restrict__ attn)
{
    extern __shared__ __align__(128) char sb[];
    const uint32_t smb = smem_u32(sb);
    float* Ssm = reinterpret_cast<float*>(sb + SSTAGE);
    const int tid = threadIdx.x, lane = tid & 31, wid = tid >> 5;
    const int h = blockIdx.x;
    const int k0t = blockIdx.y * 64;
    const int zz = blockIdx.z;
    const int b = zz >> 4;
    const int q0 = (zz & 15) * 128;
    const int bh = b * NH + h;
    const size_t hoff = (size_t)h * DK;
    const int wm = (wid >> 1) * 32, wn = (wid & 1) * 32;

    // group A: Qhi (1024 chunks, 4/thread) + Khi (512 chunks, 2/thread)
    #pragma unroll
    for (int i = 0; i < 4; i++) {
        const int chunk = tid + i * 256;
        const int r = chunk >> 3, j = chunk & 7;
        cp16(smb + r * ROWS_S + j * 16,
             Ahi + (size_t)(b * SS + q0 + r) * DM + hoff + j * 8);
    }
    #pragma unroll
    for (int i = 0; i < 2; i++) {
        const int chunk = tid + i * 256;
        const int r = chunk >> 3, j = chunk & 7;
        cp16(smb + KOFF + r * ROWS_S + j * 16,
             Bh + (size_t)(b * SS + k0t + r) * DM + hoff + j * 8);
    }
    cp_commit();

    // group B: mask tile 128x64 ints (2048 chunks, 8/thread)
    #pragma unroll
    for (int p = 0; p < 8; p++) {
        const int chunk = tid + p * 256;
        const int r = chunk >> 4, c4 = (chunk & 15) * 4;
        cp16(smb + MOFF3 + chunk * 16,
             &mask[((size_t)b * SS + q0 + r) * SS + k0t + c4]);
    }
    cp_commit();

    const uint32_t aOff = (uint32_t)((wm + (lane & 15)) * ROWS_S + (((lane >> 4) << 3)) * 2);
    const uint32_t bOff = (uint32_t)(KOFF + (wn + ((lane >> 4) << 3) + (lane & 7)) * ROWS_S
                                     + ((((lane >> 3) & 1) << 3)) * 2);

    cp_wait1();                      // inputs ready; mask still in flight
    __syncthreads();

    float acc[2][4][4] = {};
    #pragma unroll
    for (int ks = 0; ks < 64; ks += 16) {
        uint32_t ah[2][4], bh2[2][4];
        #pragma unroll
        for (int mi = 0; mi < 2; mi++)
            ldsm4(ah[mi], smb + aOff + mi * (16 * ROWS_S) + ks * 2);
        #pragma unroll
        for (int n2 = 0; n2 < 2; n2++)
            ldsm4(bh2[n2], smb + bOff + n2 * (16 * ROWS_S) + ks * 2);
        #pragma unroll
        for (int mi = 0; mi < 2; mi++)
            #pragma unroll
            for (int ni = 0; ni < 4; ni++)
                mma16816(acc[mi][ni], ah[mi], &bh2[ni >> 1][(ni & 1) * 2]);
    }

    // stage S tile to smem (separate region; no dependency on inputs)
    #pragma unroll
    for (int mi = 0; mi < 2; mi++)
        #pragma unroll
        for (int ni = 0; ni < 4; ni++) {
            #pragma unroll
            for (int half = 0; half < 2; half++) {
                const int r = wm + mi * 16 + (lane >> 2) + half * 8;
                const int c = wn + ni * 8 + (lane & 3) * 2;
                *reinterpret_cast<float2*>(&Ssm[r * SROW + c]) =
                    make_float2(acc[mi][ni][half * 2 + 0],
                                acc[mi][ni][half * 2 + 1]);
            }
        }
    cp_wait0();                      // mask tile resident
    __syncthreads();

    // coalesced streaming writes; mask read from smem only
    int bad = 0;
    #pragma unroll
    for (int p = 0; p < 8; p++) {
        const int chunk = tid + p * 256;
        const int r = chunk >> 4, c4 = (chunk & 15) * 4;
        float4 v = *reinterpret_cast<const float4*>(&Ssm[r * SROW + c4]);
        const int4 m = *reinterpret_cast<const int4*>(sb + MOFF3 + chunk * 16);
        if (m.x == 0) { v.x = -1e9f; bad = 1; }
        if (m.y == 0) { v.y = -1e9f; bad = 1; }
        if (m.z == 0) { v.z = -1e9f; bad = 1; }
        if (m.w == 0) { v.w = -1e9f; bad = 1; }
        __stcs(reinterpret_cast<float4*>(
                   &attn[((size_t)bh * SS + q0 + r) * SS + k0t + c4]), v);
    }
    if (__syncthreads_or(bad)) {
        if (tid == 0) atomicExch(&g_flag, 0);
    }
}

// ------------------------- P = K^T V (64x64 per bh), split-K -----------------
__global__ __launch_bounds__(256)
void pk_kernel()
{
    if (g_flag == 0) return;
    __shared__ float Ks[32][68];
    __shared__ float Vs[32][68];
    const int bh = blockIdx.x, split = blockIdx.y;
    const int b = bh >> 4, h = bh & 15;
    const size_t hoff = (size_t)h * DK;
    const int tid = threadIdx.x;
    const int tx = tid & 15, ty = tid >> 4;
    const __half2* khh = reinterpret_cast<const __half2*>(g_kh_hi);
    const __half2* khl = reinterpret_cast<const __half2*>(g_kh_lo);
    const __half2* vhh = reinterpret_cast<const __half2*>(g_vh_hi);
    const __half2* vhl = reinterpret_cast<const __half2*>(g_vh_lo);
    float acc[4][4] = {};
    for (int it = 0; it < 8; it++) {
        const int s0 = split * 256 + it * 32;
        __syncthreads();
        #pragma unroll
        for (int t = 0; t < 2; t++) {
            const int idx = tid + t * 256;
            const int rr = idx >> 4, c4 = idx & 15;
            const size_t g2 = ((size_t)(b * SS + s0 + rr) * DM + hoff) / 2 + c4 * 2;
            float2 kh0 = __half22float2(khh[g2]),     kl0 = __half22float2(khl[g2]);
            float2 kh1 = __half22float2(khh[g2 + 1]), kl1 = __half22float2(khl[g2 + 1]);
            Ks[rr][c4 * 4 + 0] = kh0.x + kl0.x; Ks[rr][c4 * 4 + 1] = kh0.y + kl0.y;
            Ks[rr][c4 * 4 + 2] = kh1.x + kl1.x; Ks[rr][c4 * 4 + 3] = kh1.y + kl1.y;
            float2 vh0 = __half22float2(vhh[g2]),     vl0 = __half22float2(vhl[g2]);
            float2 vh1 = __half22float2(vhh[g2 + 1]), vl1 = __half22float2(vhl[g2 + 1]);
            Vs[rr][c4 * 4 + 0] = vh0.x + vl0.x; Vs[rr][c4 * 4 + 1] = vh0.y + vl0.y;
            Vs[rr][c4 * 4 + 2] = vh1.x + vl1.x; Vs[rr][c4 * 4 + 3] = vh1.y + vl1.y;
        }
        __syncthreads();
        #pragma unroll 4
        for (int s = 0; s < 32; s++) {
            const float4 vv = *reinterpret_cast<const float4*>(&Vs[s][tx * 4]);
            #pragma unroll
            for (int i = 0; i < 4; i++) {
                const float kv = Ks[s][ty * 4 + i];
                acc[i][0] += kv * vv.x; acc[i][1] += kv * vv.y;
                acc[i][2] += kv * vv.z; acc[i][3] += kv * vv.w;
            }
        }
    }
    #pragma unroll
    for (int i = 0; i < 4; i++)
        #pragma unroll
        for (int j = 0; j < 4; j++)
            atomicAdd(&g_P[bh * (DK * DK) + (ty * 4 + i) * DK + tx * 4 + j], acc[i][j]);
}

// ------------------------- O = Qs @ P (fast path) ----------------------------
__global__ __launch_bounds__(256)
void ofast_kernel()
{
    if (g_flag == 0) return;
    __shared__ float Qs[64][68];
    __shared__ float Ps[64][64];
    const int q0 = blockIdx.x * 64;
    const int bh = blockIdx.y;
    const int b = bh >> 4, h = bh & 15;
    const size_t hoff = (size_t)h * DK;
    const int tid = threadIdx.x;
    const int tx = tid & 15, ty = tid >> 4;
    const __half2* qhh = reinterpret_cast<const __half2*>(g_qh_hi);
    const __half2* qhl = reinterpret_cast<const __half2*>(g_qh_lo);
    #pragma unroll
    for (int t = 0; t < 4; t++) {
        const int idx = tid + t * 256;
        const int rr = idx >> 4, c4 = idx & 15;
        const size_t g2 = ((size_t)(b * SS + q0 + rr) * DM + hoff) / 2 + c4 * 2;
        float2 h0 = __half22float2(qhh[g2]),     l0 = __half22float2(qhl[g2]);
        float2 h1 = __half22float2(qhh[g2 + 1]), l1 = __half22float2(qhl[g2 + 1]);
        Qs[rr][c4 * 4 + 0] = h0.x + l0.x; Qs[rr][c4 * 4 + 1] = h0.y + l0.y;
        Qs[rr][c4 * 4 + 2] = h1.x + l1.x; Qs[rr][c4 * 4 + 3] = h1.y + l1.y;
        *reinterpret_cast<float4*>(&Ps[rr][c4 * 4]) =
            reinterpret_cast<const float4*>(g_P)[(size_t)bh * (DK * DK) / 4 + rr * 16 + c4];
    }
    __syncthreads();
    float acc[4][4] = {};
    #pragma unroll 8
    for (int d = 0; d < 64; d++) {
        const float4 pv = *reinterpret_cast<const float4*>(&Ps[d][tx * 4]);
        #pragma unroll
        for (int i = 0; i < 4; i++) {
            const float qv = Qs[ty * 4 + i][d];
            acc[i][0] += qv * pv.x; acc[i][1] += qv * pv.y;
            acc[i][2] += qv * pv.z; acc[i][3] += qv * pv.w;
        }
    }
    #pragma unroll
    for (int i = 0; i < 4; i++) {
        const size_t base = (size_t)(b * SS + q0 + ty * 4 + i) * DM + hoff + tx * 4;
        __half2* ph = reinterpret_cast<__half2*>(&g_oh_hi[base]);
        ph[0] = __floats2half2_rn(acc[i][0], acc[i][1]);
        ph[1] = __floats2half2_rn(acc[i][2], acc[i][3]);
    }
}

// ------------------------- O = attn @ V (fallback) ---------------------------
__global__ __launch_bounds__(256)
void ofb_kernel(const float* __restrict__ attn)
{
    if (g_flag != 0) return;
    __shared__ float As[64][68];
    __shared__ float Vs[64][68];
    const int q0 = blockIdx.x * 64;
    const int bh = blockIdx.y;
    const int b = bh >> 4, h = bh & 15;
    const size_t hoff = (size_t)h * DK;
    const int tid = threadIdx.x;
    const int tx = tid & 15, ty = tid >> 4;
    const __half2* vhh = reinterpret_cast<const __half2*>(g_vh_hi);
    const __half2* vhl = reinterpret_cast<const __half2*>(g_vh_lo);
    float acc[4][4] = {};
    for (int k0 = 0; k0 < SS; k0 += 64) {
        __syncthreads();
        #pragma unroll
        for (int t = 0; t < 4; t++) {
            const int idx = tid + t * 256;
            const int rr = idx >> 4, c4 = idx & 15;
            *reinterpret_cast<float4*>(&As[rr][c4 * 4]) =
                reinterpret_cast<const float4*>(attn)[(((size_t)bh * SS + q0 + rr) * SS + k0) / 4 + c4];
            const size_t g2 = ((size_t)(b * SS + k0 + rr) * DM + hoff) / 2 + c4 * 2;
            float2 h0 = __half22float2(vhh[g2]),     l0 = __half22float2(vhl[g2]);
            float2 h1 = __half22float2(vhh[g2 + 1]), l1 = __half22float2(vhl[g2 + 1]);
            Vs[rr][c4 * 4 + 0] = h0.x + l0.x; Vs[rr][c4 * 4 + 1] = h0.y + l0.y;
            Vs[rr][c4 * 4 + 2] = h1.x + l1.x; Vs[rr][c4 * 4 + 3] = h1.y + l1.y;
        }
        __syncthreads();
        #pragma unroll 8
        for (int kk = 0; kk < 64; kk++) {
            const float4 vv = *reinterpret_cast<const float4*>(&Vs[kk][tx * 4]);
            #pragma unroll
            for (int i = 0; i < 4; i++) {
                const float sv = As[ty * 4 + i][kk];
                acc[i][0] += sv * vv.x; acc[i][1] += sv * vv.y;
                acc[i][2] += sv * vv.z; acc[i][3] += sv * vv.w;
            }
        }
    }
    #pragma unroll
    for (int i = 0; i < 4; i++) {
        const size_t base = (size_t)(b * SS + q0 + ty * 4 + i) * DM + hoff + tx * 4;
        __half2* ph = reinterpret_cast<__half2*>(&g_oh_hi[base]);
        ph[0] = __floats2half2_rn(acc[i][0], acc[i][1]);
        ph[1] = __floats2half2_rn(acc[i][2], acc[i][3]);
    }
}

// ---------------------------------------------------------------------------
extern "C" void kernel_launch(void* const* d_in, const int* in_sizes, int n_in,
                              void* d_out, int out_size)
{
    const float* q     = (const float*)d_in[0];
    const float* k     = (const float*)d_in[1];
    const float* v     = (const float*)d_in[2];
    const int*   mask  = (const int*)  d_in[3];
    const float* Wq    = (const float*)d_in[4];
    const float* Wk    = (const float*)d_in[5];
    const float* Wv    = (const float*)d_in[6];
    const float* Wfc   = (const float*)d_in[7];
    const float* gamma = (const float*)d_in[8];
    const float* beta  = (const float*)d_in[9];
    float* out = (float*)d_out;
    float* attn = ((long long)out_size >= (long long)OUT_ELEMS + ATTN_ELEMS)
                      ? out + OUT_ELEMS : nullptr;

    void* p;
    #define SYM(T, name, sym) cudaGetSymbolAddress(&p, sym); T* name = (T*)p
    SYM(fp16, qn_hi, g_qn_hi);
    SYM(fp16, ki_hi, g_ki_hi);
    SYM(fp16, vi_hi, g_vi_hi);
    SYM(fp16, wq_hi, g_wq_hi);
    SYM(fp16, wk_hi, g_wk_hi);
    SYM(fp16, wv_hi, g_wv_hi);
    SYM(fp16, wf_hi, g_wf_hi);
    SYM(fp16, qh_hi, g_qh_hi); SYM(fp16, qh_lo, g_qh_lo);
    SYM(fp16, kh_hi, g_kh_hi); SYM(fp16, kh_lo, g_kh_lo);
    SYM(fp16, vh_hi, g_vh_hi); SYM(fp16, vh_lo, g_vh_lo);
    SYM(fp16, oh_hi, g_oh_hi);
    #undef SYM

    cudaFuncSetAttribute(tgemm, cudaFuncAttributeMaxDynamicSharedMemorySize, TG_SMEM);
    cudaFuncSetAttribute(sgemm_attn, cudaFuncAttributeMaxDynamicSharedMemorySize, SA_SMEM);

    // prep
    initk<<<512, 256>>>();
    if (!attn) maskchk<<<2048, 256>>>(mask);
    ln_kernel<<<NROWS, 256>>>(q, gamma, beta, qn_hi);
    cvt2k<<<dim3(NROWS * DM / 4 / 256, 2), 256>>>(k, v, ki_hi, vi_hi, NROWS * DM / 4);
    wprep4<<<dim3(32, 32, 4), dim3(32, 8)>>>(Wq, Wk, Wv, Wfc,
                                             wq_hi, wk_hi, wv_hi, wf_hi);

    // projections (fp16 1-term, 128x256 tile -> 128 blocks = 1 wave)
    dim3 gg(DM / 256, NROWS / 128);
    tgemm<<<gg, 256, TG_SMEM>>>(qn_hi, wq_hi, nullptr, qh_hi, qh_lo, nullptr, DM, DM);
    tgemm<<<gg, 256, TG_SMEM>>>(ki_hi, wk_hi, nullptr, kh_hi, kh_lo, nullptr, DM, DM);
    tgemm<<<gg, 256, TG_SMEM>>>(vi_hi, wv_hi, nullptr, vh_hi, vh_lo, nullptr, DM, DM);

    // attn scores: 128x64 tiles, occ 2, head-major grid for mask L2 reuse
    if (attn)
        sgemm_attn<<<dim3(NH, SS / 64, BB * (SS / 128)), 256, SA_SMEM>>>(
            qh_hi, kh_hi, mask, attn);

    // O: fast path (mask all-ones) or fallback
    pk_kernel<<<dim3(BB * NH, 8), 256>>>();
    ofast_kernel<<<dim3(SS / 64, BB * NH), 256>>>();
    if (attn)
        ofb_kernel<<<dim3(SS / 64, BB * NH), 256>>>(attn);

    // fc + residual (1-term)
    tgemm<<<gg, 256, TG_SMEM>>>(oh_hi, wf_hi, out, nullptr, nullptr, q, DM, DM);
}

// round 17
// speedup vs baseline: 1.8134x; 1.0645x over previous
#include <cuda_runtime.h>
#include <cuda_fp16.h>
#include <cstdint>

#define BB 2
#define SS 2048
#define DM 1024
#define NH 16
#define DK 64
#define NROWS (BB * SS)
#define OUT_ELEMS (NROWS * DM)
#define ATTN_ELEMS (2LL * 16 * 2048 * 2048)
#define INV_TEMP 0.35355339059327373f

typedef __half fp16;

// ------------------------- device scratch (no allocs) -----------------------
__device__ __align__(128) fp16  g_qn_hi[NROWS * DM];
__device__ __align__(128) fp16  g_ki_hi[NROWS * DM];
__device__ __align__(128) fp16  g_vi_hi[NROWS * DM];
__device__ __align__(128) fp16  g_wq_hi[DM * DM];
__device__ __align__(128) fp16  g_wk_hi[DM * DM];
__device__ __align__(128) fp16  g_wv_hi[DM * DM];
__device__ __align__(128) fp16  g_wf_hi[DM * DM];
__device__ __align__(128) fp16  g_qh_hi[NROWS * DM];
__device__ __align__(128) fp16  g_kh_hi[NROWS * DM];
__device__ __align__(128) fp16  g_vh_hi[NROWS * DM];
__device__ __align__(128) fp16  g_oh_hi[NROWS * DM];
__device__ __align__(128) float g_P[BB * NH * DK * DK];
__device__ int g_flag;

// ------------------------- helpers ------------------------------------------
__device__ __forceinline__ uint32_t smem_u32(const void* p) {
    uint32_t a;
    asm("{ .reg .u64 t; cvta.to.shared.u64 t, %1; cvt.u32.u64 %0, t; }"
        : "=r"(a) : "l"(p));
    return a;
}
__device__ __forceinline__ void cp16(uint32_t saddr, const void* g) {
    asm volatile("cp.async.cg.shared.global [%0], [%1], 16;"
                 :: "r"(saddr), "l"(g) : "memory");
}
__device__ __forceinline__ void cp_commit() {
    asm volatile("cp.async.commit_group;" ::: "memory");
}
__device__ __forceinline__ void cp_wait0() {
    asm volatile("cp.async.wait_group 0;" ::: "memory");
}
__device__ __forceinline__ void cp_wait1() {
    asm volatile("cp.async.wait_group 1;" ::: "memory");
}
__device__ __forceinline__ void cp_wait2() {
    asm volatile("cp.async.wait_group 2;" ::: "memory");
}
__device__ __forceinline__ void ldsm4(uint32_t* r, uint32_t addr) {
    asm volatile("ldmatrix.sync.aligned.m8n8.x4.shared.b16 {%0,%1,%2,%3}, [%4];"
                 : "=r"(r[0]), "=r"(r[1]), "=r"(r[2]), "=r"(r[3]) : "r"(addr));
}
__device__ __forceinline__ void mma16816(float* d, const uint32_t* a,
                                         const uint32_t* b) {
    asm volatile(
        "mma.sync.aligned.m16n8k16.row.col.f32.f16.f16.f32 "
        "{%0,%1,%2,%3}, {%4,%5,%6,%7}, {%8,%9}, {%0,%1,%2,%3};"
        : "+f"(d[0]), "+f"(d[1]), "+f"(d[2]), "+f"(d[3])
        : "r"(a[0]), "r"(a[1]), "r"(a[2]), "r"(a[3]), "r"(b[0]), "r"(b[1]));
}

// ------------------------- small prep kernels --------------------------------
__global__ void initk() {
    int i = blockIdx.x * 256 + threadIdx.x;
    if (i < BB * NH * DK * DK) g_P[i] = 0.0f;
    if (i == 0) g_flag = 1;
}

// fallback full-mask check (only used when attn buffer absent)
__global__ void maskchk(const int* __restrict__ mask) {
    const int4* m4 = reinterpret_cast<const int4*>(mask);
    const size_t total = (size_t)BB * SS * SS / 4;
    size_t i = (size_t)blockIdx.x * 256 + threadIdx.x;
    size_t stride = (size_t)gridDim.x * 256;
    int bad = 0;
    for (size_t j = i; j < total; j += stride) {
        int4 m = __ldcs(&m4[j]);
        if (!(m.x && m.y && m.z && m.w)) bad = 1;
    }
    if (bad) g_flag = 0;
}

__global__ void ln_kernel(const float* __restrict__ q,
                          const float* __restrict__ gamma,
                          const float* __restrict__ beta,
                          fp16* __restrict__ out_hi) {
    __shared__ float red[16];
    const int row = blockIdx.x;
    const int tid = threadIdx.x;
    const float4 v = reinterpret_cast<const float4*>(q)[row * 256 + tid];
    float s  = v.x + v.y + v.z + v.w;
    float s2 = v.x * v.x + v.y * v.y + v.z * v.z + v.w * v.w;
    #pragma unroll
    for (int o = 16; o > 0; o >>= 1) {
        s  += __shfl_xor_sync(0xffffffffu, s,  o);
        s2 += __shfl_xor_sync(0xffffffffu, s2, o);
    }
    if ((tid & 31) == 0) { red[tid >> 5] = s; red[8 + (tid >> 5)] = s2; }
    __syncthreads();
    if (tid < 32) {
        s  = (tid < 8) ? red[tid]     : 0.0f;
        s2 = (tid < 8) ? red[8 + tid] : 0.0f;
        #pragma unroll
        for (int o = 4; o > 0; o >>= 1) {
            s  += __shfl_xor_sync(0xffffffffu, s,  o);
            s2 += __shfl_xor_sync(0xffffffffu, s2, o);
        }
        if (tid == 0) { red[0] = s; red[8] = s2; }
    }
    __syncthreads();
    const float mu   = red[0] * (1.0f / 1024.0f);
    const float var  = red[8] * (1.0f / 1024.0f) - mu * mu;
    const float rstd = rsqrtf(var + 1e-6f);
    const float4 g  = reinterpret_cast<const float4*>(gamma)[tid];
    const float4 bb = reinterpret_cast<const float4*>(beta)[tid];
    float y0 = ((v.x - mu) * rstd * g.x + bb.x) * INV_TEMP;
    float y1 = ((v.y - mu) * rstd * g.y + bb.y) * INV_TEMP;
    float y2 = ((v.z - mu) * rstd * g.z + bb.z) * INV_TEMP;
    float y3 = ((v.w - mu) * rstd * g.w + bb.w) * INV_TEMP;
    __half2* oh = reinterpret_cast<__half2*>(out_hi);
    const int b2 = (row * 256 + tid) * 2;
    oh[b2]     = __floats2half2_rn(y0, y1);
    oh[b2 + 1] = __floats2half2_rn(y2, y3);
}

// fp32 -> fp16 for k and v in one launch (blockIdx.y selects)
__global__ void cvt2k(const float* __restrict__ k, const float* __restrict__ v,
                      fp16* __restrict__ khi, fp16* __restrict__ vhi, int n4) {
    int i = blockIdx.x * 256 + threadIdx.x;
    if (i >= n4) return;
    const float* x = blockIdx.y ? v : k;
    fp16* hi = blockIdx.y ? vhi : khi;
    float4 t = reinterpret_cast<const float4*>(x)[i];
    reinterpret_cast<__half2*>(hi)[i * 2]     = __floats2half2_rn(t.x, t.y);
    reinterpret_cast<__half2*>(hi)[i * 2 + 1] = __floats2half2_rn(t.z, t.w);
}

// W[K][N] -> WT[n][k] fp16 for 4 weight matrices (blockIdx.z selects)
__global__ void wprep4(const float* __restrict__ W0, const float* __restrict__ W1,
                       const float* __restrict__ W2, const float* __restrict__ W3,
                       fp16* __restrict__ T0, fp16* __restrict__ T1,
                       fp16* __restrict__ T2, fp16* __restrict__ T3) {
    __shared__ float t[32][33];
    const float* W = (blockIdx.z == 0) ? W0 : (blockIdx.z == 1) ? W1
                   : (blockIdx.z == 2) ? W2 : W3;
    fp16* T = (blockIdx.z == 0) ? T0 : (blockIdx.z == 1) ? T1
            : (blockIdx.z == 2) ? T2 : T3;
    const int n0 = blockIdx.x * 32, k0 = blockIdx.y * 32;
    const int tx = threadIdx.x, ty = threadIdx.y;
    #pragma unroll
    for (int r = 0; r < 4; r++)
        t[ty + r * 8][tx] = W[(size_t)(k0 + ty + r * 8) * DM + n0 + tx];
    __syncthreads();
    #pragma unroll
    for (int r = 0; r < 4; r++) {
        const int nl = ty + r * 8;
        T[(size_t)(n0 + nl) * DM + k0 + tx] = __float2half_rn(t[tx][nl]);
    }
}

// ------------------------- mma.sync GEMM shared body -------------------------
// 128(M)x256(N) CTA, BK=32, 3-stage, warp tile 64x64. K=N=1024.
#define ROWB 80
#define ABUF (128 * ROWB)            // 10240
#define BBUF (256 * ROWB)            // 20480
#define STAGEB (ABUF + BBUF)         // 30720
#define TG_SMEM (3 * STAGEB)         // 92160

template <typename EPI>
__device__ __forceinline__ void tg_body(const fp16* A, const fp16* Bh,
                                        int bm, int bn, EPI epi)
{
    extern __shared__ __align__(128) char sb[];
    const uint32_t smb = smem_u32(sb);
    const int tid = threadIdx.x, lane = tid & 31, wid = tid >> 5;
    const int wm = (wid >> 2) * 64, wn = (wid & 3) * 64;

    uint32_t ldSm[6]; const fp16* ldG[6];
    #pragma unroll
    for (int i = 0; i < 6; i++) {
        const int isB = (i >= 2);
        const int chunk = tid + (isB ? (i - 2) : i) * 256;
        const int r = chunk >> 2, j = chunk & 3;
        ldSm[i] = smb + (isB ? ABUF : 0) + r * ROWB + j * 16;
        ldG[i] = (isB ? Bh + (size_t)(bn + r) * DM : A + (size_t)(bm + r) * DM) + j * 8;
    }

    const uint32_t aOff = (uint32_t)((wm + (lane & 15)) * ROWB + (((lane >> 4) << 3)) * 2);
    const uint32_t bOff = (uint32_t)(ABUF + (wn + ((lane >> 4) << 3) + (lane & 7)) * ROWB
                                     + ((((lane >> 3) & 1) << 3)) * 2);

    float acc[4][8][4] = {};
    const int NT = DM / 32;

    #pragma unroll
    for (int s = 0; s < 2; s++) {
        #pragma unroll
        for (int i = 0; i < 6; i++) cp16(ldSm[i] + s * STAGEB, ldG[i] + s * 32);
        cp_commit();
    }

    int stage = 0;
    for (int t = 0; t < NT; t++) {
        if (t + 2 < NT) {
            const int ps = (stage + 2) % 3;
            const int kc = (t + 2) * 32;
            #pragma unroll
            for (int i = 0; i < 6; i++) cp16(ldSm[i] + ps * STAGEB, ldG[i] + kc);
            cp_commit();
            cp_wait2();
        } else if (t + 1 < NT) {
            cp_wait1();
        } else {
            cp_wait0();
        }
        __syncthreads();

        const uint32_t st = smb + stage * STAGEB;
        #pragma unroll
        for (int ks = 0; ks < 32; ks += 16) {
            uint32_t ah[4][4], bh2[4][4];
            #pragma unroll
            for (int mi = 0; mi < 4; mi++)
                ldsm4(ah[mi], st + aOff + mi * (16 * ROWB) + ks * 2);
            #pragma unroll
            for (int n2 = 0; n2 < 4; n2++)
                ldsm4(bh2[n2], st + bOff + n2 * (16 * ROWB) + ks * 2);
            #pragma unroll
            for (int mi = 0; mi < 4; mi++)
                #pragma unroll
                for (int ni = 0; ni < 8; ni++)
                    mma16816(acc[mi][ni], ah[mi], &bh2[ni >> 1][(ni & 1) * 2]);
        }
        __syncthreads();
        stage = (stage + 1) % 3;
    }

    #pragma unroll
    for (int mi = 0; mi < 4; mi++)
        #pragma unroll
        for (int ni = 0; ni < 8; ni++)
            #pragma unroll
            for (int half = 0; half < 2; half++) {
                const int r = bm + wm + mi * 16 + (lane >> 2) + half * 8;
                const int c = bn + wn + ni * 8 + (lane & 3) * 2;
                epi(r, c, acc[mi][ni][half * 2 + 0], acc[mi][ni][half * 2 + 1]);
            }
}

// fused QKV: grid.z selects (A, B, C)
__global__ __launch_bounds__(256, 1)
void tgemm_qkv()
{
    const int z = blockIdx.z;
    const fp16* A  = (z == 0) ? g_qn_hi : (z == 1) ? g_ki_hi : g_vi_hi;
    const fp16* Bh = (z == 0) ? g_wq_hi : (z == 1) ? g_wk_hi : g_wv_hi;
    fp16* C        = (z == 0) ? g_qh_hi : (z == 1) ? g_kh_hi : g_vh_hi;
    tg_body(A, Bh, blockIdx.y * 128, blockIdx.x * 256,
            [C](int r, int c, float d0, float d1) {
                *reinterpret_cast<__half2*>(&C[(size_t)r * DM + c]) =
                    __floats2half2_rn(d0, d1);
            });
}

// fc + residual -> fp32 out
__global__ __launch_bounds__(256, 1)
void tgemm_fc(float* __restrict__ out, const float* __restrict__ resid)
{
    tg_body(g_oh_hi, g_wf_hi, blockIdx.y * 128, blockIdx.x * 256,
            [out, resid](int r, int c, float d0, float d1) {
                const size_t idx = (size_t)r * DM + c;
                const float2 q2 = *reinterpret_cast<const float2*>(&resid[idx]);
                *reinterpret_cast<float2*>(&out[idx]) =
                    make_float2(d0 + q2.x, d1 + q2.y);
            });
}

// ------------------------- S = Qhi Khi^T, 128(q) x 64(k) tile ----------------
#define ROWS_S 144
#define BUFQ1 (128 * ROWS_S)            // 18432 (Qhi)
#define KOFF  BUFQ1                     // Khi (9216)
#define SSTAGE (BUFQ1 + 64 * ROWS_S)    // 27648
#define SROW 68
#define MOFF3 (SSTAGE + 128 * SROW * 4) // 62464
#define SA_SMEM (MOFF3 + 128 * 64 * 4)  // 95232

__global__ __launch_bounds__(256, 2)
void sgemm_attn(const fp16* __restrict__ Ahi, const fp16* __restrict__ Bh,
                const int* __restrict__ mask, float* __restrict__ attn)
{
    extern __shared__ __align__(128) char sb[];
    const uint32_t smb = smem_u32(sb);
    float* Ssm = reinterpret_cast<float*>(sb + SSTAGE);
    const int tid = threadIdx.x, lane = tid & 31, wid = tid >> 5;
    const int h = blockIdx.x;
    const int k0t = blockIdx.y * 64;
    const int zz = blockIdx.z;
    const int b = zz >> 4;
    const int q0 = (zz & 15) * 128;
    const int bh = b * NH + h;
    const size_t hoff = (size_t)h * DK;
    const int wm = (wid >> 1) * 32, wn = (wid & 1) * 32;

    #pragma unroll
    for (int i = 0; i < 4; i++) {
        const int chunk = tid + i * 256;
        const int r = chunk >> 3, j = chunk & 7;
        cp16(smb + r * ROWS_S + j * 16,
             Ahi + (size_t)(b * SS + q0 + r) * DM + hoff + j * 8);
    }
    #pragma unroll
    for (int i = 0; i < 2; i++) {
        const int chunk = tid + i * 256;
        const int r = chunk >> 3, j = chunk & 7;
        cp16(smb + KOFF + r * ROWS_S + j * 16,
             Bh + (size_t)(b * SS + k0t + r) * DM + hoff + j * 8);
    }
    cp_commit();

    #pragma unroll
    for (int p = 0; p < 8; p++) {
        const int chunk = tid + p * 256;
        const int r = chunk >> 4, c4 = (chunk & 15) * 4;
        cp16(smb + MOFF3 + chunk * 16,
             &mask[((size_t)b * SS + q0 + r) * SS + k0t + c4]);
    }
    cp_commit();

    const uint32_t aOff = (uint32_t)((wm + (lane & 15)) * ROWS_S + (((lane >> 4) << 3)) * 2);
    const uint32_t bOff = (uint32_t)(KOFF + (wn + ((lane >> 4) << 3) + (lane & 7)) * ROWS_S
                                     + ((((lane >> 3) & 1) << 3)) * 2);

    cp_wait1();
    __syncthreads();

    float acc[2][4][4] = {};
    #pragma unroll
    for (int ks = 0; ks < 64; ks += 16) {
        uint32_t ah[2][4], bh2[2][4];
        #pragma unroll
        for (int mi = 0; mi < 2; mi++)
            ldsm4(ah[mi], smb + aOff + mi * (16 * ROWS_S) + ks * 2);
        #pragma unroll
        for (int n2 = 0; n2 < 2; n2++)
            ldsm4(bh2[n2], smb + bOff + n2 * (16 * ROWS_S) + ks * 2);
        #pragma unroll
        for (int mi = 0; mi < 2; mi++)
            #pragma unroll
            for (int ni = 0; ni < 4; ni++)
                mma16816(acc[mi][ni], ah[mi], &bh2[ni >> 1][(ni & 1) * 2]);
    }

    #pragma unroll
    for (int mi = 0; mi < 2; mi++)
        #pragma unroll
        for (int ni = 0; ni < 4; ni++)
            #pragma unroll
            for (int half = 0; half < 2; half++) {
                const int r = wm + mi * 16 + (lane >> 2) + half * 8;
                const int c = wn + ni * 8 + (lane & 3) * 2;
                *reinterpret_cast<float2*>(&Ssm[r * SROW + c]) =
                    make_float2(acc[mi][ni][half * 2 + 0],
                                acc[mi][ni][half * 2 + 1]);
            }
    cp_wait0();
    __syncthreads();

    int bad = 0;
    #pragma unroll
    for (int p = 0; p < 8; p++) {
        const int chunk = tid + p * 256;
        const int r = chunk >> 4, c4 = (chunk & 15) * 4;
        float4 v = *reinterpret_cast<const float4*>(&Ssm[r * SROW + c4]);
        const int4 m = *reinterpret_cast<const int4*>(sb + MOFF3 + chunk * 16);
        if (m.x == 0) { v.x = -1e9f; bad = 1; }
        if (m.y == 0) { v.y = -1e9f; bad = 1; }
        if (m.z == 0) { v.z = -1e9f; bad = 1; }
        if (m.w == 0) { v.w = -1e9f; bad = 1; }
        __stcs(reinterpret_cast<float4*>(
                   &attn[((size_t)bh * SS + q0 + r) * SS + k0t + c4]), v);
    }
    if (__syncthreads_or(bad)) {
        if (tid == 0) atomicExch(&g_flag, 0);
    }
}

// ------------------------- P = K^T V (64x64 per bh), split-K -----------------
__global__ __launch_bounds__(256)
void pk_kernel()
{
    if (g_flag == 0) return;
    __shared__ float Ks[32][68];
    __shared__ float Vs[32][68];
    const int bh = blockIdx.x, split = blockIdx.y;
    const int b = bh >> 4, h = bh & 15;
    const size_t hoff = (size_t)h * DK;
    const int tid = threadIdx.x;
    const int tx = tid & 15, ty = tid >> 4;
    const __half2* khh = reinterpret_cast<const __half2*>(g_kh_hi);
    const __half2* vhh = reinterpret_cast<const __half2*>(g_vh_hi);
    float acc[4][4] = {};
    for (int it = 0; it < 8; it++) {
        const int s0 = split * 256 + it * 32;
        __syncthreads();
        #pragma unroll
        for (int t = 0; t < 2; t++) {
            const int idx = tid + t * 256;
            const int rr = idx >> 4, c4 = idx & 15;
            const size_t g2 = ((size_t)(b * SS + s0 + rr) * DM + hoff) / 2 + c4 * 2;
            float2 k0 = __half22float2(khh[g2]);
            float2 k1 = __half22float2(khh[g2 + 1]);
            Ks[rr][c4 * 4 + 0] = k0.x; Ks[rr][c4 * 4 + 1] = k0.y;
            Ks[rr][c4 * 4 + 2] = k1.x; Ks[rr][c4 * 4 + 3] = k1.y;
            float2 v0 = __half22float2(vhh[g2]);
            float2 v1 = __half22float2(vhh[g2 + 1]);
            Vs[rr][c4 * 4 + 0] = v0.x; Vs[rr][c4 * 4 + 1] = v0.y;
            Vs[rr][c4 * 4 + 2] = v1.x; Vs[rr][c4 * 4 + 3] = v1.y;
        }
        __syncthreads();
        #pragma unroll 4
        for (int s = 0; s < 32; s++) {
            const float4 vv = *reinterpret_cast<const float4*>(&Vs[s][tx * 4]);
            #pragma unroll
            for (int i = 0; i < 4; i++) {
                const float kv = Ks[s][ty * 4 + i];
                acc[i][0] += kv * vv.x; acc[i][1] += kv * vv.y;
                acc[i][2] += kv * vv.z; acc[i][3] += kv * vv.w;
            }
        }
    }
    #pragma unroll
    for (int i = 0; i < 4; i++)
        #pragma unroll
        for (int j = 0; j < 4; j++)
            atomicAdd(&g_P[bh * (DK * DK) + (ty * 4 + i) * DK + tx * 4 + j], acc[i][j]);
}

// ------------------------- O = Qs @ P (fast path) ----------------------------
__global__ __launch_bounds__(256)
void ofast_kernel()
{
    if (g_flag == 0) return;
    __shared__ float Qs[64][68];
    __shared__ float Ps[64][64];
    const int q0 = blockIdx.x * 64;
    const int bh = blockIdx.y;
    const int b = bh >> 4, h = bh & 15;
    const size_t hoff = (size_t)h * DK;
    const int tid = threadIdx.x;
    const int tx = tid & 15, ty = tid >> 4;
    const __half2* qhh = reinterpret_cast<const __half2*>(g_qh_hi);
    #pragma unroll
    for (int t = 0; t < 4; t++) {
        const int idx = tid + t * 256;
        const int rr = idx >> 4, c4 = idx & 15;
        const size_t g2 = ((size_t)(b * SS + q0 + rr) * DM + hoff) / 2 + c4 * 2;
        float2 h0 = __half22float2(qhh[g2]);
        float2 h1 = __half22float2(qhh[g2 + 1]);
        Qs[rr][c4 * 4 + 0] = h0.x; Qs[rr][c4 * 4 + 1] = h0.y;
        Qs[rr][c4 * 4 + 2] = h1.x; Qs[rr][c4 * 4 + 3] = h1.y;
        *reinterpret_cast<float4*>(&Ps[rr][c4 * 4]) =
            reinterpret_cast<const float4*>(g_P)[(size_t)bh * (DK * DK) / 4 + rr * 16 + c4];
    }
    __syncthreads();
    float acc[4][4] = {};
    #pragma unroll 8
    for (int d = 0; d < 64; d++) {
        const float4 pv = *reinterpret_cast<const float4*>(&Ps[d][tx * 4]);
        #pragma unroll
        for (int i = 0; i < 4; i++) {
            const float qv = Qs[ty * 4 + i][d];
            acc[i][0] += qv * pv.x; acc[i][1] += qv * pv.y;
            acc[i][2] += qv * pv.z; acc[i][3] += qv * pv.w;
        }
    }
    #pragma unroll
    for (int i = 0; i < 4; i++) {
        const size_t base = (size_t)(b * SS + q0 + ty * 4 + i) * DM + hoff + tx * 4;
        __half2* ph = reinterpret_cast<__half2*>(&g_oh_hi[base]);
        ph[0] = __floats2half2_rn(acc[i][0], acc[i][1]);
        ph[1] = __floats2half2_rn(acc[i][2], acc[i][3]);
    }
}

// ------------------------- O = attn @ V (fallback) ---------------------------
__global__ __launch_bounds__(256)
void ofb_kernel(const float* __restrict__ attn)
{
    if (g_flag != 0) return;
    __shared__ float As[64][68];
    __shared__ float Vs[64][68];
    const int q0 = blockIdx.x * 64;
    const int bh = blockIdx.y;
    const int b = bh >> 4, h = bh & 15;
    const size_t hoff = (size_t)h * DK;
    const int tid = threadIdx.x;
    const int tx = tid & 15, ty = tid >> 4;
    const __half2* vhh = reinterpret_cast<const __half2*>(g_vh_hi);
    float acc[4][4] = {};
    for (int k0 = 0; k0 < SS; k0 += 64) {
        __syncthreads();
        #pragma unroll
        for (int t = 0; t < 4; t++) {
            const int idx = tid + t * 256;
            const int rr = idx >> 4, c4 = idx & 15;
            *reinterpret_cast<float4*>(&As[rr][c4 * 4]) =
                reinterpret_cast<const float4*>(attn)[(((size_t)bh * SS + q0 + rr) * SS + k0) / 4 + c4];
            const size_t g2 = ((size_t)(b * SS + k0 + rr) * DM + hoff) / 2 + c4 * 2;
            float2 h0 = __half22float2(vhh[g2]);
            float2 h1 = __half22float2(vhh[g2 + 1]);
            Vs[rr][c4 * 4 + 0] = h0.x; Vs[rr][c4 * 4 + 1] = h0.y;
            Vs[rr][c4 * 4 + 2] = h1.x; Vs[rr][c4 * 4 + 3] = h1.y;
        }
        __syncthreads();
        #pragma unroll 8
        for (int kk = 0; kk < 64; kk++) {
            const float4 vv = *reinterpret_cast<const float4*>(&Vs[kk][tx * 4]);
            #pragma unroll
            for (int i = 0; i < 4; i++) {
                const float sv = As[ty * 4 + i][kk];
                acc[i][0] += sv * vv.x; acc[i][1] += sv * vv.y;
                acc[i][2] += sv * vv.z; acc[i][3] += sv * vv.w;
            }
        }
    }
    #pragma unroll
    for (int i = 0; i < 4; i++) {
        const size_t base = (size_t)(b * SS + q0 + ty * 4 + i) * DM + hoff + tx * 4;
        __half2* ph = reinterpret_cast<__half2*>(&g_oh_hi[base]);
        ph[0] = __floats2half2_rn(acc[i][0], acc[i][1]);
        ph[1] = __floats2half2_rn(acc[i][2], acc[i][3]);
    }
}

// ---------------------------------------------------------------------------
extern "C" void kernel_launch(void* const* d_in, const int* in_sizes, int n_in,
                              void* d_out, int out_size)
{
    const float* q     = (const float*)d_in[0];
    const float* k     = (const float*)d_in[1];
    const float* v     = (const float*)d_in[2];
    const int*   mask  = (const int*)  d_in[3];
    const float* Wq    = (const float*)d_in[4];
    const float* Wk    = (const float*)d_in[5];
    const float* Wv    = (const float*)d_in[6];
    const float* Wfc   = (const float*)d_in[7];
    const float* gamma = (const float*)d_in[8];
    const float* beta  = (const float*)d_in[9];
    float* out = (float*)d_out;
    float* attn = ((long long)out_size >= (long long)OUT_ELEMS + ATTN_ELEMS)
                      ? out + OUT_ELEMS : nullptr;

    void* p;
    #define SYM(T, name, sym) cudaGetSymbolAddress(&p, sym); T* name = (T*)p
    SYM(fp16, qn_hi, g_qn_hi);
    SYM(fp16, ki_hi, g_ki_hi);
    SYM(fp16, vi_hi, g_vi_hi);
    SYM(fp16, wq_hi, g_wq_hi);
    SYM(fp16, wk_hi, g_wk_hi);
    SYM(fp16, wv_hi, g_wv_hi);
    SYM(fp16, wf_hi, g_wf_hi);
    SYM(fp16, qh_hi, g_qh_hi);
    SYM(fp16, kh_hi, g_kh_hi);
    #undef SYM

    cudaFuncSetAttribute(tgemm_qkv, cudaFuncAttributeMaxDynamicSharedMemorySize, TG_SMEM);
    cudaFuncSetAttribute(tgemm_fc, cudaFuncAttributeMaxDynamicSharedMemorySize, TG_SMEM);
    cudaFuncSetAttribute(sgemm_attn, cudaFuncAttributeMaxDynamicSharedMemorySize, SA_SMEM);

    // prep
    initk<<<512, 256>>>();
    if (!attn) maskchk<<<2048, 256>>>(mask);
    ln_kernel<<<NROWS, 256>>>(q, gamma, beta, qn_hi);
    cvt2k<<<dim3(NROWS * DM / 4 / 256, 2), 256>>>(k, v, ki_hi, vi_hi, NROWS * DM / 4);
    wprep4<<<dim3(32, 32, 4), dim3(32, 8)>>>(Wq, Wk, Wv, Wfc,
                                             wq_hi, wk_hi, wv_hi, wf_hi);

    // fused QKV projections (one launch, z selects)
    tgemm_qkv<<<dim3(DM / 256, NROWS / 128, 3), 256, TG_SMEM>>>();

    // attn scores: 128x64 tiles, occ 2, head-major grid for mask L2 reuse
    if (attn)
        sgemm_attn<<<dim3(NH, SS / 64, BB * (SS / 128)), 256, SA_SMEM>>>(
            qh_hi, kh_hi, mask, attn);

    // O: fast path (mask all-ones) or fallback
    pk_kernel<<<dim3(BB * NH, 8), 256>>>();
    ofast_kernel<<<dim3(SS / 64, BB * NH), 256>>>();
    if (attn)
        ofb_kernel<<<dim3(SS / 64, BB * NH), 256>>>(attn);

    // fc + residual
    tgemm_fc<<<dim3(DM / 256, NROWS / 128), 256, TG_SMEM>>>(out, q);
}